// round 5
// baseline (speedup 1.0000x reference)
#include <cuda_runtime.h>
#include <math.h>

#define B 8
#define C 48
#define C3 144
#define HH 256
#define WW 256
#define NPIX (HH*WW)
#define HEADS 8
#define DH 6
#define SCALE 0.40824829046386296f
#define EPSN 1e-12f

/* ---------------- main fused tile config ---------------- */
#define TX 32
#define TY 16
#define TPX (TX*TY)          /* 512 */
#define HX 34
#define HY 18
#define HALO (HX*HY)         /* 612 */
#define NT 512
#define TILES_X (WW/TX)      /* 8 */
#define TILES_Y (HH/TY)      /* 16 */
#define NTIL (TILES_X*TILES_Y) /* 128 */

/* scratch */
__device__ float g_v[(size_t)B*C*NPIX];
__device__ float g_part[B*NTIL*HEADS*48];
__device__ float g_M[B*C*C];

/* dynamic smem layout for k_main (float offsets) */
#define OFF_XS 0
#define SZ_XS (C*HALO)            /* 29376 */
#define OFF_WP (OFF_XS+SZ_XS)
#define SZ_WP (C*C3)              /* 6912: wP[cin][g*12+j] */
#define OFF_WD (OFF_WP+SZ_WP)
#define SZ_WD (C3*9)              /* 1296: wdP[(g*12+j)*9+t] */
#define OFF_PB (OFF_WD+SZ_WD)
#define SZ_PB (12*HALO)           /* 7344 */
#define OFF_DW (OFF_PB+SZ_PB)
#define SZ_DW (12*TPX)            /* 6144 */
#define SM_FLOATS (OFF_DW+SZ_DW)  /* 51072 -> 204288 B */

__device__ __forceinline__ void cout_to_gj(int cout, int& g, int& j)
{
    if (cout < C)            { g = cout / DH;          j = cout % DH; }
    else if (cout < 2*C)     { g = (cout - C) / DH;    j = DH + (cout - C) % DH; }
    else                     { g = 8 + (cout - 2*C)/12; j = (cout - 2*C) % 12; }
}

__global__ __launch_bounds__(NT, 1)
void k_main(const float* __restrict__ x, const float* __restrict__ wqkv,
            const float* __restrict__ wdw)
{
    extern __shared__ float sm[];
    float* xs  = sm + OFF_XS;
    float* wP  = sm + OFF_WP;
    float* wdP = sm + OFF_WD;
    float* pb  = sm + OFF_PB;
    float* dws = sm + OFF_DW;

    const int tid = threadIdx.x;
    const int b = blockIdx.z;
    const int ox0 = blockIdx.x * TX, oy0 = blockIdx.y * TY;

    /* stage permuted pointwise weights: wP[cin*144 + g*12 + j] */
    for (int i = tid; i < C3*C; i += NT) {
        int cout = i / C, cin = i % C;
        int g, j; cout_to_gj(cout, g, j);
        wP[cin*C3 + g*12 + j] = wqkv[i];
    }
    /* stage permuted dw weights */
    for (int i = tid; i < C3*9; i += NT) {
        int cch = i / 9, t = i % 9;
        int g, j; cout_to_gj(cch, g, j);
        wdP[(g*12 + j)*9 + t] = wdw[i];
    }
    /* stage x halo (zero pad) */
    const float* xb = x + (size_t)b*C*NPIX;
    for (int i = tid; i < C*HALO; i += NT) {
        int c = i / HALO, p = i % HALO;
        int hy = p / HX, hx = p % HX;
        int gy = oy0 - 1 + hy, gx = ox0 - 1 + hx;
        float v = 0.f;
        if ((unsigned)gy < (unsigned)HH && (unsigned)gx < (unsigned)WW)
            v = xb[(size_t)c*NPIX + gy*WW + gx];
        xs[i] = v;
    }

    const int oy = tid / TX, ox = tid % TX;
    const int p0 = tid;
    const bool has1 = (tid < HALO - TPX);     /* tid < 100 */
    const int p1 = has1 ? tid + TPX : tid;
    const int warp = tid >> 5, lane = tid & 31;
    const int tileLin = blockIdx.y * TILES_X + blockIdx.x;

    for (int g = 0; g < 12; ++g) {
        __syncthreads();   /* pb free (prev dw reads done); xs/w staged (first iter) */

        /* pointwise: 12 channels x 2 halo px per thread */
        float acc0[12], acc1[12];
        #pragma unroll
        for (int j = 0; j < 12; ++j) { acc0[j] = 0.f; acc1[j] = 0.f; }

        const float* wg = wP + g*12;
        #pragma unroll 2
        for (int cin = 0; cin < C; ++cin) {
            float xv0 = xs[cin*HALO + p0];
            float xv1 = xs[cin*HALO + p1];
            const float4* w4 = reinterpret_cast<const float4*>(wg + cin*C3);
            float4 wa = w4[0], wb = w4[1], wc = w4[2];
            acc0[0] += wa.x*xv0;  acc1[0] += wa.x*xv1;
            acc0[1] += wa.y*xv0;  acc1[1] += wa.y*xv1;
            acc0[2] += wa.z*xv0;  acc1[2] += wa.z*xv1;
            acc0[3] += wa.w*xv0;  acc1[3] += wa.w*xv1;
            acc0[4] += wb.x*xv0;  acc1[4] += wb.x*xv1;
            acc0[5] += wb.y*xv0;  acc1[5] += wb.y*xv1;
            acc0[6] += wb.z*xv0;  acc1[6] += wb.z*xv1;
            acc0[7] += wb.w*xv0;  acc1[7] += wb.w*xv1;
            acc0[8] += wc.x*xv0;  acc1[8] += wc.x*xv1;
            acc0[9] += wc.y*xv0;  acc1[9] += wc.y*xv1;
            acc0[10] += wc.z*xv0; acc1[10] += wc.z*xv1;
            acc0[11] += wc.w*xv0; acc1[11] += wc.w*xv1;
        }
        #pragma unroll
        for (int j = 0; j < 12; ++j) {
            pb[j*HALO + p0] = acc0[j];
            if (has1) pb[j*HALO + p1] = acc1[j];
        }
        __syncthreads();

        /* depthwise 3x3 at this thread's output pixel, 12 channels */
        if (g < 8) {
            #pragma unroll
            for (int j = 0; j < 12; ++j) {
                const float* w = wdP + (g*12 + j)*9;
                const float* p = pb + j*HALO + oy*HX + ox;
                dws[j*TPX + tid] =
                      w[0]*p[0]      + w[1]*p[1]        + w[2]*p[2]
                    + w[3]*p[HX]     + w[4]*p[HX+1]     + w[5]*p[HX+2]
                    + w[6]*p[2*HX]   + w[7]*p[2*HX+1]   + w[8]*p[2*HX+2];
            }
            __syncthreads();
            /* gram partials: 48 combos over 16 warps x 3 */
            #pragma unroll
            for (int i = 0; i < 3; ++i) {
                int combo = warp*3 + i;
                const float *pa2, *pb2;
                if (combo < 36)      { pa2 = dws + (combo/6)*TPX;      pb2 = dws + (6 + combo%6)*TPX; }
                else if (combo < 42) { pa2 = dws + (combo-36)*TPX;     pb2 = pa2; }
                else                 { pa2 = dws + (6 + combo-42)*TPX; pb2 = pa2; }
                float s = 0.f;
                #pragma unroll
                for (int k = 0; k < TPX/32; ++k)
                    s += pa2[lane + k*32] * pb2[lane + k*32];
                #pragma unroll
                for (int off = 16; off; off >>= 1)
                    s += __shfl_down_sync(0xffffffffu, s, off);
                if (lane == 0)
                    g_part[((size_t)(b*NTIL + tileLin)*HEADS + g)*48 + combo] = s;
            }
            /* dws overwritten only after next group's 2 barriers -> safe */
        } else {
            float* vb = g_v + (size_t)b*C*NPIX + (oy0+oy)*WW + (ox0+ox);
            #pragma unroll
            for (int j = 0; j < 12; ++j) {
                const float* w = wdP + (g*12 + j)*9;
                const float* p = pb + j*HALO + oy*HX + ox;
                float dv =
                      w[0]*p[0]      + w[1]*p[1]        + w[2]*p[2]
                    + w[3]*p[HX]     + w[4]*p[HX+1]     + w[5]*p[HX+2]
                    + w[6]*p[2*HX]   + w[7]*p[2*HX+1]   + w[8]*p[2*HX+2];
                vb[(size_t)((g-8)*12 + j)*NPIX] = dv;
            }
        }
    }
}

/* ===== reduce partials + softmax + fold attn into M = Wproj*blockdiag ===== */
__global__ __launch_bounds__(384)
void k_attn(const float* __restrict__ wproj)
{
    const int b = blockIdx.x, tid = threadIdx.x;
    __shared__ float gram_s[HEADS*48];
    __shared__ float attn_s[HEADS][36];

    /* deterministic reduce over 128 tiles */
    if (tid < HEADS*48) {
        const float* p = g_part + (size_t)b*NTIL*(HEADS*48) + tid;
        float s = 0.f;
        for (int t = 0; t < NTIL; ++t) s += p[(size_t)t*(HEADS*48)];
        gram_s[tid] = s;
    }
    __syncthreads();

    if (tid < HEADS*DH) {
        int h = tid / DH, d = tid % DH;
        const float* g = gram_s + h*48;
        float qn = fmaxf(sqrtf(g[36 + d]), EPSN);
        float a[6]; float m = -1e30f;
        #pragma unroll
        for (int e = 0; e < 6; ++e) {
            float kn = fmaxf(sqrtf(g[42 + e]), EPSN);
            a[e] = g[d*6+e] * SCALE / (qn * kn);
            m = fmaxf(m, a[e]);
        }
        float s = 0.f;
        #pragma unroll
        for (int e = 0; e < 6; ++e) { a[e] = expf(a[e]-m); s += a[e]; }
        float inv = 1.f / s;
        #pragma unroll
        for (int e = 0; e < 6; ++e) attn_s[h][d*6+e] = a[e]*inv;
    }
    __syncthreads();

    for (int idx = tid; idx < C*C; idx += blockDim.x) {
        int c = idx / C, c2 = idx % C;
        int h2 = c2 / DH, e = c2 % DH;
        float s = 0.f;
        #pragma unroll
        for (int d = 0; d < 6; ++d)
            s += wproj[c*C + h2*DH + d] * attn_s[h2][d*6+e];
        g_M[b*C*C + idx] = s;
    }
}

/* ============ out = M[b] @ v, register-tiled (4px x 12 cout) ============ */
#define PRN 128
#define PR_NT 128   /* 32 x 4 */

__global__ __launch_bounds__(PR_NT, 6)
void k_proj(float* __restrict__ out)
{
    __shared__ float vs[C*PRN];     /* [cin][128] */
    __shared__ float MsT[C*C];      /* [cin][cout] */

    const int tid = threadIdx.x;
    const int tx = tid & 31, ty = tid >> 5;
    const int b = blockIdx.y;
    const int n0 = blockIdx.x * PRN;

    const float* gv = g_v + (size_t)b*C*NPIX + n0;
    for (int i = tid; i < C*PRN; i += PR_NT)
        vs[i] = gv[(size_t)(i >> 7)*NPIX + (i & 127)];
    const float* gM = g_M + b*C*C;
    for (int i = tid; i < C*C; i += PR_NT) {
        int c = i / C, c2 = i % C;
        MsT[c2*C + c] = gM[i];
    }
    __syncthreads();

    float4 acc[12];
    #pragma unroll
    for (int j = 0; j < 12; ++j) acc[j] = make_float4(0.f,0.f,0.f,0.f);

    const float4* xcol = reinterpret_cast<const float4*>(vs) + tx;
    const float*  wrow = MsT + ty*12;

    #pragma unroll 4
    for (int cin = 0; cin < C; ++cin) {
        float4 xv = xcol[cin*(PRN/4)];
        const float4* w4 = reinterpret_cast<const float4*>(wrow + cin*C);
        float4 w0 = w4[0], w1 = w4[1], w2 = w4[2];
        acc[0].x += w0.x*xv.x; acc[0].y += w0.x*xv.y; acc[0].z += w0.x*xv.z; acc[0].w += w0.x*xv.w;
        acc[1].x += w0.y*xv.x; acc[1].y += w0.y*xv.y; acc[1].z += w0.y*xv.z; acc[1].w += w0.y*xv.w;
        acc[2].x += w0.z*xv.x; acc[2].y += w0.z*xv.y; acc[2].z += w0.z*xv.z; acc[2].w += w0.z*xv.w;
        acc[3].x += w0.w*xv.x; acc[3].y += w0.w*xv.y; acc[3].z += w0.w*xv.z; acc[3].w += w0.w*xv.w;
        acc[4].x += w1.x*xv.x; acc[4].y += w1.x*xv.y; acc[4].z += w1.x*xv.z; acc[4].w += w1.x*xv.w;
        acc[5].x += w1.y*xv.x; acc[5].y += w1.y*xv.y; acc[5].z += w1.y*xv.z; acc[5].w += w1.y*xv.w;
        acc[6].x += w1.z*xv.x; acc[6].y += w1.z*xv.y; acc[6].z += w1.z*xv.z; acc[6].w += w1.z*xv.w;
        acc[7].x += w1.w*xv.x; acc[7].y += w1.w*xv.y; acc[7].z += w1.w*xv.z; acc[7].w += w1.w*xv.w;
        acc[8].x += w2.x*xv.x; acc[8].y += w2.x*xv.y; acc[8].z += w2.x*xv.z; acc[8].w += w2.x*xv.w;
        acc[9].x += w2.y*xv.x; acc[9].y += w2.y*xv.y; acc[9].z += w2.y*xv.z; acc[9].w += w2.y*xv.w;
        acc[10].x += w2.z*xv.x; acc[10].y += w2.z*xv.y; acc[10].z += w2.z*xv.z; acc[10].w += w2.z*xv.w;
        acc[11].x += w2.w*xv.x; acc[11].y += w2.w*xv.y; acc[11].z += w2.w*xv.z; acc[11].w += w2.w*xv.w;
    }

    float* ob = out + (size_t)b*C*NPIX + n0 + tx*4;
    #pragma unroll
    for (int j = 0; j < 12; ++j) {
        int cout = ty*12 + j;
        *reinterpret_cast<float4*>(ob + (size_t)cout*NPIX) = acc[j];
    }
}

extern "C" void kernel_launch(void* const* d_in, const int* in_sizes, int n_in,
                              void* d_out, int out_size)
{
    const float* x     = (const float*)d_in[0];
    const float* wqkv  = (const float*)d_in[1];
    const float* wdw   = (const float*)d_in[2];
    const float* wproj = (const float*)d_in[3];
    float* out = (float*)d_out;

    cudaFuncSetAttribute(k_main, cudaFuncAttributeMaxDynamicSharedMemorySize,
                         SM_FLOATS * (int)sizeof(float));

    dim3 gm(TILES_X, TILES_Y, B);
    k_main<<<gm, NT, SM_FLOATS * sizeof(float)>>>(x, wqkv, wdw);

    k_attn<<<B, 384>>>(wproj);

    dim3 gp(NPIX/PRN, B);
    k_proj<<<gp, PR_NT>>>(out);
}

// round 6
// speedup vs baseline: 1.1078x; 1.1078x over previous
#include <cuda_runtime.h>
#include <math.h>

#define B 8
#define C 48
#define C3 144
#define HH 256
#define WW 256
#define NPIX (HH*WW)
#define HEADS 8
#define DH 6
#define SCALE 0.40824829046386296f
#define EPSN 1e-12f

/* ---- scratch ---- */
__device__ float g_qkv[(size_t)B*C3*NPIX];   /* pw output */
__device__ float g_v[(size_t)B*C*NPIX];      /* dw(v) */
#define NTIL 64                               /* 64 row-strips of 4 rows */
__device__ float g_part[B*NTIL*HEADS*48];
__device__ float g_M[B*C*C];

/* ================= k_pw: qkv[144][n] = W[144][48] @ x[48][n] ============ */
#define PWN 128
#define PW_TX 32
#define PW_TY 12
#define PW_NT (PW_TX*PW_TY)    /* 384 */
#define PW_XS 0
#define PW_WT (48*PWN)
#define PW_SMF (48*PWN + 48*C3)   /* 13056 floats = 52224 B */

__global__ __launch_bounds__(PW_NT, 2)
void k_pw(const float* __restrict__ x, const float* __restrict__ wqkv)
{
    extern __shared__ float sm[];
    float* xs = sm + PW_XS;
    float* wT = sm + PW_WT;

    const int tid = threadIdx.x;
    const int tx = tid & 31, ty = tid >> 5;
    const int b = blockIdx.y;
    const int n0 = blockIdx.x * PWN;

    const float* xb = x + (size_t)b*C*NPIX + n0;
    for (int i = tid; i < C*PWN; i += PW_NT)
        xs[i] = xb[(size_t)(i >> 7)*NPIX + (i & 127)];
    for (int i = tid; i < C3*C; i += PW_NT)
        wT[(i % C)*C3 + (i / C)] = wqkv[i];
    __syncthreads();

    float4 acc[12];
    #pragma unroll
    for (int j = 0; j < 12; ++j) acc[j] = make_float4(0.f,0.f,0.f,0.f);

    const float4* xcol = reinterpret_cast<const float4*>(xs) + tx;
    const float*  wrow = wT + ty*12;

    #pragma unroll 4
    for (int cin = 0; cin < C; ++cin) {
        float4 xv = xcol[cin*(PWN/4)];
        const float4* w4 = reinterpret_cast<const float4*>(wrow + cin*C3);
        float4 w0 = w4[0], w1 = w4[1], w2 = w4[2];
        acc[0].x += w0.x*xv.x; acc[0].y += w0.x*xv.y; acc[0].z += w0.x*xv.z; acc[0].w += w0.x*xv.w;
        acc[1].x += w0.y*xv.x; acc[1].y += w0.y*xv.y; acc[1].z += w0.y*xv.z; acc[1].w += w0.y*xv.w;
        acc[2].x += w0.z*xv.x; acc[2].y += w0.z*xv.y; acc[2].z += w0.z*xv.z; acc[2].w += w0.z*xv.w;
        acc[3].x += w0.w*xv.x; acc[3].y += w0.w*xv.y; acc[3].z += w0.w*xv.z; acc[3].w += w0.w*xv.w;
        acc[4].x += w1.x*xv.x; acc[4].y += w1.x*xv.y; acc[4].z += w1.x*xv.z; acc[4].w += w1.x*xv.w;
        acc[5].x += w1.y*xv.x; acc[5].y += w1.y*xv.y; acc[5].z += w1.y*xv.z; acc[5].w += w1.y*xv.w;
        acc[6].x += w1.z*xv.x; acc[6].y += w1.z*xv.y; acc[6].z += w1.z*xv.z; acc[6].w += w1.z*xv.w;
        acc[7].x += w1.w*xv.x; acc[7].y += w1.w*xv.y; acc[7].z += w1.w*xv.z; acc[7].w += w1.w*xv.w;
        acc[8].x += w2.x*xv.x; acc[8].y += w2.x*xv.y; acc[8].z += w2.x*xv.z; acc[8].w += w2.x*xv.w;
        acc[9].x += w2.y*xv.x; acc[9].y += w2.y*xv.y; acc[9].z += w2.y*xv.z; acc[9].w += w2.y*xv.w;
        acc[10].x += w2.z*xv.x; acc[10].y += w2.z*xv.y; acc[10].z += w2.z*xv.z; acc[10].w += w2.z*xv.w;
        acc[11].x += w2.w*xv.x; acc[11].y += w2.w*xv.y; acc[11].z += w2.w*xv.z; acc[11].w += w2.w*xv.w;
    }

    float* ob = g_qkv + (size_t)b*C3*NPIX + n0 + tx*4;
    #pragma unroll
    for (int j = 0; j < 12; ++j) {
        int cout = ty*12 + j;
        *reinterpret_cast<float4*>(ob + (size_t)cout*NPIX) = acc[j];
    }
}

/* ===== k_dwr: row-strip depthwise 3x3 + gram partials / v store ===== */
/* block: 4 output rows x 256 cols x 12 channels; grid (64 strips, 12 groups, B) */
#define DR 4                 /* output rows per strip */
#define DHR 6                /* staged rows (incl halo) */
#define DWCOL 258            /* 256 + 2 pad cols */
#define DWR_NT 256
/* smem floats: halo 12*6*258 = 18576, red 8*48 = 384, wds 108 -> 19068 */
#define DWR_HALO 0
#define DWR_RED (12*DHR*DWCOL)
#define DWR_WDS (DWR_RED + 8*48)
#define DWR_SMF (DWR_WDS + 12*9)      /* 19176 floats = 76704 B */

__global__ __launch_bounds__(DWR_NT, 2)
void k_dwr(const float* __restrict__ wdw)
{
    extern __shared__ float sm[];
    float* halo = sm + DWR_HALO;
    float* red  = sm + DWR_RED;
    float* wds  = sm + DWR_WDS;

    const int tid = threadIdx.x;
    const int strip = blockIdx.x;         /* 0..63 */
    const int g = blockIdx.y;             /* 0..11 */
    const int b = blockIdx.z;
    const int r0 = strip * DR;
    const bool isHead = (g < 8);

    int chan[12];
    if (isHead) {
        #pragma unroll
        for (int j = 0; j < 6; ++j) { chan[j] = g*DH + j; chan[6+j] = C + g*DH + j; }
    } else {
        #pragma unroll
        for (int j = 0; j < 12; ++j) chan[j] = 2*C + (g-8)*12 + j;
    }

    if (tid < 12*9) wds[tid] = wdw[chan[tid/9]*9 + tid%9];

    /* stage 12 channels x 6 rows x 256 cols, coalesced; pad col 0 and 257 */
    const float* qb = g_qkv + (size_t)b*C3*NPIX;
    for (int i = tid; i < 12*DHR*256; i += DWR_NT) {
        int ch  = i / (DHR*256);
        int rem = i - ch*(DHR*256);
        int rr  = rem >> 8;
        int col = rem & 255;
        int grow = r0 - 1 + rr;
        float v = 0.f;
        if ((unsigned)grow < (unsigned)HH)
            v = qb[(size_t)chan[ch]*NPIX + grow*WW + col];
        halo[(ch*DHR + rr)*DWCOL + col + 1] = v;
    }
    if (tid < 12*DHR) {
        halo[tid*DWCOL] = 0.f;
        halo[tid*DWCOL + DWCOL - 1] = 0.f;
    }
    __syncthreads();

    if (isHead) {
        float acc[48];
        #pragma unroll
        for (int i = 0; i < 48; ++i) acc[i] = 0.f;

        #pragma unroll
        for (int r = 0; r < DR; ++r) {
            float dv[12];
            #pragma unroll
            for (int j = 0; j < 12; ++j) {
                const float* w = wds + j*9;
                const float* p = halo + (j*DHR + r)*DWCOL + tid;
                dv[j] = w[0]*p[0]        + w[1]*p[1]          + w[2]*p[2]
                      + w[3]*p[DWCOL]    + w[4]*p[DWCOL+1]    + w[5]*p[DWCOL+2]
                      + w[6]*p[2*DWCOL]  + w[7]*p[2*DWCOL+1]  + w[8]*p[2*DWCOL+2];
            }
            #pragma unroll
            for (int d = 0; d < 6; ++d) {
                #pragma unroll
                for (int e = 0; e < 6; ++e)
                    acc[d*6+e] += dv[d] * dv[6+e];
                acc[36+d] += dv[d] * dv[d];
                acc[42+d] += dv[6+d] * dv[6+d];
            }
        }
        /* reduce 48 accs across block (deterministic) */
        const int warp = tid >> 5, lane = tid & 31;
        #pragma unroll
        for (int i = 0; i < 48; ++i) {
            float s = acc[i];
            #pragma unroll
            for (int off = 16; off; off >>= 1)
                s += __shfl_down_sync(0xffffffffu, s, off);
            if (lane == 0) red[warp*48 + i] = s;
        }
        __syncthreads();
        if (tid < 48) {
            float s = 0.f;
            #pragma unroll
            for (int w = 0; w < 8; ++w) s += red[w*48 + tid];
            g_part[((size_t)(b*NTIL + strip)*HEADS + g)*48 + tid] = s;
        }
    } else {
        float* vb = g_v + (size_t)b*C*NPIX + r0*WW + tid;
        #pragma unroll
        for (int r = 0; r < DR; ++r) {
            #pragma unroll
            for (int j = 0; j < 12; ++j) {
                const float* w = wds + j*9;
                const float* p = halo + (j*DHR + r)*DWCOL + tid;
                float dv = w[0]*p[0]        + w[1]*p[1]          + w[2]*p[2]
                         + w[3]*p[DWCOL]    + w[4]*p[DWCOL+1]    + w[5]*p[DWCOL+2]
                         + w[6]*p[2*DWCOL]  + w[7]*p[2*DWCOL+1]  + w[8]*p[2*DWCOL+2];
                vb[(size_t)((g-8)*12 + j)*NPIX + r*WW] = dv;
            }
        }
    }
}

/* ===== reduce partials + softmax + fold attn into M = Wproj*blockdiag ===== */
__global__ __launch_bounds__(384)
void k_attn(const float* __restrict__ wproj)
{
    const int b = blockIdx.x, tid = threadIdx.x;
    __shared__ float gram_s[HEADS*48];
    __shared__ float attn_s[HEADS][36];

    if (tid < HEADS*48) {
        const float* p = g_part + (size_t)b*NTIL*(HEADS*48) + tid;
        float s = 0.f;
        for (int t = 0; t < NTIL; ++t) s += p[(size_t)t*(HEADS*48)];
        gram_s[tid] = s;
    }
    __syncthreads();

    if (tid < HEADS*DH) {
        int h = tid / DH, d = tid % DH;
        const float* g = gram_s + h*48;
        float qn = fmaxf(sqrtf(g[36 + d]), EPSN);
        float a[6]; float m = -1e30f;
        #pragma unroll
        for (int e = 0; e < 6; ++e) {
            float kn = fmaxf(sqrtf(g[42 + e]), EPSN);
            a[e] = g[d*6+e] * SCALE / (qn * kn);
            m = fmaxf(m, a[e]);
        }
        float s = 0.f;
        #pragma unroll
        for (int e = 0; e < 6; ++e) { a[e] = expf(a[e]-m); s += a[e]; }
        float inv = 1.f / s;
        #pragma unroll
        for (int e = 0; e < 6; ++e) attn_s[h][d*6+e] = a[e]*inv;
    }
    __syncthreads();

    for (int idx = tid; idx < C*C; idx += blockDim.x) {
        int c = idx / C, c2 = idx % C;
        int h2 = c2 / DH, e = c2 % DH;
        float s = 0.f;
        #pragma unroll
        for (int d = 0; d < 6; ++d)
            s += wproj[c*C + h2*DH + d] * attn_s[h2][d*6+e];
        g_M[b*C*C + idx] = s;
    }
}

/* ============ out = M[b] @ v, register-tiled (4px x 12 cout) ============ */
#define PRN 128
#define PR_NT 128

__global__ __launch_bounds__(PR_NT, 6)
void k_proj(float* __restrict__ out)
{
    __shared__ float vs[C*PRN];
    __shared__ float MsT[C*C];

    const int tid = threadIdx.x;
    const int tx = tid & 31, ty = tid >> 5;
    const int b = blockIdx.y;
    const int n0 = blockIdx.x * PRN;

    const float* gv = g_v + (size_t)b*C*NPIX + n0;
    for (int i = tid; i < C*PRN; i += PR_NT)
        vs[i] = gv[(size_t)(i >> 7)*NPIX + (i & 127)];
    const float* gM = g_M + b*C*C;
    for (int i = tid; i < C*C; i += PR_NT) {
        int c = i / C, c2 = i % C;
        MsT[c2*C + c] = gM[i];
    }
    __syncthreads();

    float4 acc[12];
    #pragma unroll
    for (int j = 0; j < 12; ++j) acc[j] = make_float4(0.f,0.f,0.f,0.f);

    const float4* xcol = reinterpret_cast<const float4*>(vs) + tx;
    const float*  wrow = MsT + ty*12;

    #pragma unroll 4
    for (int cin = 0; cin < C; ++cin) {
        float4 xv = xcol[cin*(PRN/4)];
        const float4* w4 = reinterpret_cast<const float4*>(wrow + cin*C);
        float4 w0 = w4[0], w1 = w4[1], w2 = w4[2];
        acc[0].x += w0.x*xv.x; acc[0].y += w0.x*xv.y; acc[0].z += w0.x*xv.z; acc[0].w += w0.x*xv.w;
        acc[1].x += w0.y*xv.x; acc[1].y += w0.y*xv.y; acc[1].z += w0.y*xv.z; acc[1].w += w0.y*xv.w;
        acc[2].x += w0.z*xv.x; acc[2].y += w0.z*xv.y; acc[2].z += w0.z*xv.z; acc[2].w += w0.z*xv.w;
        acc[3].x += w0.w*xv.x; acc[3].y += w0.w*xv.y; acc[3].z += w0.w*xv.z; acc[3].w += w0.w*xv.w;
        acc[4].x += w1.x*xv.x; acc[4].y += w1.x*xv.y; acc[4].z += w1.x*xv.z; acc[4].w += w1.x*xv.w;
        acc[5].x += w1.y*xv.x; acc[5].y += w1.y*xv.y; acc[5].z += w1.y*xv.z; acc[5].w += w1.y*xv.w;
        acc[6].x += w1.z*xv.x; acc[6].y += w1.z*xv.y; acc[6].z += w1.z*xv.z; acc[6].w += w1.z*xv.w;
        acc[7].x += w1.w*xv.x; acc[7].y += w1.w*xv.y; acc[7].z += w1.w*xv.z; acc[7].w += w1.w*xv.w;
        acc[8].x += w2.x*xv.x; acc[8].y += w2.x*xv.y; acc[8].z += w2.x*xv.z; acc[8].w += w2.x*xv.w;
        acc[9].x += w2.y*xv.x; acc[9].y += w2.y*xv.y; acc[9].z += w2.y*xv.z; acc[9].w += w2.y*xv.w;
        acc[10].x += w2.z*xv.x; acc[10].y += w2.z*xv.y; acc[10].z += w2.z*xv.z; acc[10].w += w2.z*xv.w;
        acc[11].x += w2.w*xv.x; acc[11].y += w2.w*xv.y; acc[11].z += w2.w*xv.z; acc[11].w += w2.w*xv.w;
    }

    float* ob = out + (size_t)b*C*NPIX + n0 + tx*4;
    #pragma unroll
    for (int j = 0; j < 12; ++j) {
        int cout = ty*12 + j;
        *reinterpret_cast<float4*>(ob + (size_t)cout*NPIX) = acc[j];
    }
}

extern "C" void kernel_launch(void* const* d_in, const int* in_sizes, int n_in,
                              void* d_out, int out_size)
{
    const float* x     = (const float*)d_in[0];
    const float* wqkv  = (const float*)d_in[1];
    const float* wdw   = (const float*)d_in[2];
    const float* wproj = (const float*)d_in[3];
    float* out = (float*)d_out;

    cudaFuncSetAttribute(k_pw, cudaFuncAttributeMaxDynamicSharedMemorySize,
                         PW_SMF * (int)sizeof(float));
    cudaFuncSetAttribute(k_dwr, cudaFuncAttributeMaxDynamicSharedMemorySize,
                         DWR_SMF * (int)sizeof(float));

    dim3 gpw(NPIX/PWN, B);
    k_pw<<<gpw, PW_NT, PW_SMF * sizeof(float)>>>(x, wqkv);

    dim3 gdw(NTIL, 12, B);
    k_dwr<<<gdw, DWR_NT, DWR_SMF * sizeof(float)>>>(wdw);

    k_attn<<<B, 384>>>(wproj);

    dim3 gp(NPIX/PRN, B);
    k_proj<<<gp, PR_NT>>>(out);
}

// round 7
// speedup vs baseline: 1.3900x; 1.2548x over previous
#include <cuda_runtime.h>
#include <math.h>

#define B 8
#define C 48
#define C3 144
#define HH 256
#define WW 256
#define NPIX (HH*WW)
#define HEADS 8
#define DH 6
#define SCALE 0.40824829046386296f
#define EPSN 1e-12f

/* ---- scratch ---- */
__device__ float g_qkv[(size_t)B*C3*NPIX];
__device__ float g_v[(size_t)B*C*NPIX];
#define NTIL 128        /* 8x16 tiles of 32x16 */
__device__ float g_part[B*NTIL*HEADS*48];
__device__ float g_M[B*C*C];

/* ================= k_pw: qkv[144][n] = W[144][48] @ x[48][n] ============ */
#define PWN 128
#define PW_TX 32
#define PW_TY 12
#define PW_NT (PW_TX*PW_TY)    /* 384 */
#define PW_XS 0
#define PW_WT (48*PWN)
#define PW_SMF (48*PWN + 48*C3)   /* 13056 floats = 52224 B */

__global__ __launch_bounds__(PW_NT, 2)
void k_pw(const float* __restrict__ x, const float* __restrict__ wqkv)
{
    extern __shared__ float sm[];
    float* xs = sm + PW_XS;
    float* wT = sm + PW_WT;

    const int tid = threadIdx.x;
    const int tx = tid & 31, ty = tid >> 5;
    const int b = blockIdx.y;
    const int n0 = blockIdx.x * PWN;

    const float* xb = x + (size_t)b*C*NPIX + n0;
    for (int i = tid; i < C*PWN; i += PW_NT)
        xs[i] = xb[(size_t)(i >> 7)*NPIX + (i & 127)];
    for (int i = tid; i < C3*C; i += PW_NT)
        wT[(i % C)*C3 + (i / C)] = wqkv[i];
    __syncthreads();

    float4 acc[12];
    #pragma unroll
    for (int j = 0; j < 12; ++j) acc[j] = make_float4(0.f,0.f,0.f,0.f);

    const float4* xcol = reinterpret_cast<const float4*>(xs) + tx;
    const float*  wrow = wT + ty*12;

    #pragma unroll 4
    for (int cin = 0; cin < C; ++cin) {
        float4 xv = xcol[cin*(PWN/4)];
        const float4* w4 = reinterpret_cast<const float4*>(wrow + cin*C3);
        float4 w0 = w4[0], w1 = w4[1], w2 = w4[2];
        acc[0].x += w0.x*xv.x; acc[0].y += w0.x*xv.y; acc[0].z += w0.x*xv.z; acc[0].w += w0.x*xv.w;
        acc[1].x += w0.y*xv.x; acc[1].y += w0.y*xv.y; acc[1].z += w0.y*xv.z; acc[1].w += w0.y*xv.w;
        acc[2].x += w0.z*xv.x; acc[2].y += w0.z*xv.y; acc[2].z += w0.z*xv.z; acc[2].w += w0.z*xv.w;
        acc[3].x += w0.w*xv.x; acc[3].y += w0.w*xv.y; acc[3].z += w0.w*xv.z; acc[3].w += w0.w*xv.w;
        acc[4].x += w1.x*xv.x; acc[4].y += w1.x*xv.y; acc[4].z += w1.x*xv.z; acc[4].w += w1.x*xv.w;
        acc[5].x += w1.y*xv.x; acc[5].y += w1.y*xv.y; acc[5].z += w1.y*xv.z; acc[5].w += w1.y*xv.w;
        acc[6].x += w1.z*xv.x; acc[6].y += w1.z*xv.y; acc[6].z += w1.z*xv.z; acc[6].w += w1.z*xv.w;
        acc[7].x += w1.w*xv.x; acc[7].y += w1.w*xv.y; acc[7].z += w1.w*xv.z; acc[7].w += w1.w*xv.w;
        acc[8].x += w2.x*xv.x; acc[8].y += w2.x*xv.y; acc[8].z += w2.x*xv.z; acc[8].w += w2.x*xv.w;
        acc[9].x += w2.y*xv.x; acc[9].y += w2.y*xv.y; acc[9].z += w2.y*xv.z; acc[9].w += w2.y*xv.w;
        acc[10].x += w2.z*xv.x; acc[10].y += w2.z*xv.y; acc[10].z += w2.z*xv.z; acc[10].w += w2.z*xv.w;
        acc[11].x += w2.w*xv.x; acc[11].y += w2.w*xv.y; acc[11].z += w2.w*xv.z; acc[11].w += w2.w*xv.w;
    }

    float* ob = g_qkv + (size_t)b*C3*NPIX + n0 + tx*4;
    #pragma unroll
    for (int j = 0; j < 12; ++j) {
        int cout = ty*12 + j;
        *reinterpret_cast<float4*>(ob + (size_t)cout*NPIX) = acc[j];
    }
}

/* ===== k_dw32: 32x16-tile depthwise 3x3 + gram partials / v store ===== */
#define TX 32
#define TY 16
#define TPX (TX*TY)      /* 512 */
#define HX 34
#define HY 18
#define HALO (HX*HY)     /* 612 */
#define DW_NT 512
/* dyn smem floats: halo 12*612=7344, dws 12*512=6144, wds 108 */
#define DW_HALO 0
#define DW_DWS (12*HALO)
#define DW_WDS (DW_DWS + 12*TPX)
#define DW_SMF (DW_WDS + 12*9)     /* 13596 floats = 54384 B */

__global__ __launch_bounds__(DW_NT, 2)
void k_dw32(const float* __restrict__ wdw)
{
    extern __shared__ float sm[];
    float* halo = sm + DW_HALO;
    float* dws  = sm + DW_DWS;
    float* wds  = sm + DW_WDS;

    const int tid = threadIdx.x;
    const int z = blockIdx.z;
    const int b = z / 14, g = z % 14;
    const bool isHead = (g < 8);
    const int nch = isHead ? 12 : 8;
    const int oy0 = blockIdx.y * TY, ox0 = blockIdx.x * TX;
    const int oy = tid / TX, ox = tid & 31;

    int chan[12];
    if (isHead) {
        #pragma unroll
        for (int j = 0; j < 6; ++j) { chan[j] = g*DH + j; chan[6+j] = C + g*DH + j; }
    } else {
        #pragma unroll
        for (int j = 0; j < 8; ++j) chan[j] = 2*C + (g-8)*8 + j;
        chan[8] = chan[9] = chan[10] = chan[11] = chan[0];
    }

    if (tid < nch*9) wds[tid] = wdw[chan[tid/9]*9 + tid%9];

    /* stage halos (zero-pad SAME) */
    const float* qb = g_qkv + (size_t)b*C3*NPIX;
    for (int i = tid; i < nch*HALO; i += DW_NT) {
        int ch = i / HALO, p = i - ch*HALO;
        int hy = p / HX, hx = p - hy*HX;
        int gy = oy0 - 1 + hy, gx = ox0 - 1 + hx;
        float v = 0.f;
        if ((unsigned)gy < (unsigned)HH && (unsigned)gx < (unsigned)WW)
            v = qb[(size_t)chan[ch]*NPIX + gy*WW + gx];
        halo[ch*HALO + p] = v;
    }
    __syncthreads();

    if (isHead) {
        #pragma unroll
        for (int ch = 0; ch < 12; ++ch) {
            const float* w = wds + ch*9;
            const float* p = halo + ch*HALO + oy*HX + ox;
            dws[ch*TPX + tid] =
                  w[0]*p[0]      + w[1]*p[1]        + w[2]*p[2]
                + w[3]*p[HX]     + w[4]*p[HX+1]     + w[5]*p[HX+2]
                + w[6]*p[2*HX]   + w[7]*p[2*HX+1]   + w[8]*p[2*HX+2];
        }
        __syncthreads();
        const int warp = tid >> 5, lane = tid & 31;
        const int tileLin = blockIdx.y * (WW/TX) + blockIdx.x;
        #pragma unroll
        for (int i = 0; i < 3; ++i) {
            int combo = warp*3 + i;
            const float *pa, *pb;
            if (combo < 36)      { pa = dws + (combo/6)*TPX;      pb = dws + (6 + combo%6)*TPX; }
            else if (combo < 42) { pa = dws + (combo-36)*TPX;     pb = pa; }
            else                 { pa = dws + (6 + combo-42)*TPX; pb = pa; }
            float s = 0.f;
            #pragma unroll
            for (int k = 0; k < TPX/32; ++k)
                s += pa[lane + k*32] * pb[lane + k*32];
            #pragma unroll
            for (int off = 16; off; off >>= 1)
                s += __shfl_down_sync(0xffffffffu, s, off);
            if (lane == 0)
                g_part[((size_t)(b*NTIL + tileLin)*HEADS + g)*48 + combo] = s;
        }
    } else {
        float* vb = g_v + (size_t)b*C*NPIX + (oy0+oy)*WW + (ox0+ox);
        #pragma unroll
        for (int ch = 0; ch < 8; ++ch) {
            const float* w = wds + ch*9;
            const float* p = halo + ch*HALO + oy*HX + ox;
            float dv = w[0]*p[0]      + w[1]*p[1]        + w[2]*p[2]
                     + w[3]*p[HX]     + w[4]*p[HX+1]     + w[5]*p[HX+2]
                     + w[6]*p[2*HX]   + w[7]*p[2*HX+1]   + w[8]*p[2*HX+2];
            vb[(size_t)((g-8)*8 + ch)*NPIX] = dv;
        }
    }
}

/* ===== reduce partials + softmax + fold attn into M = Wproj*blockdiag ===== */
__global__ __launch_bounds__(384)
void k_attn(const float* __restrict__ wproj)
{
    const int b = blockIdx.x, tid = threadIdx.x;
    __shared__ float gram_s[HEADS*48];
    __shared__ float attn_s[HEADS][36];

    if (tid < HEADS*48) {
        const float* p = g_part + (size_t)b*NTIL*(HEADS*48) + tid;
        float s = 0.f;
        for (int t = 0; t < NTIL; ++t) s += p[(size_t)t*(HEADS*48)];
        gram_s[tid] = s;
    }
    __syncthreads();

    if (tid < HEADS*DH) {
        int h = tid / DH, d = tid % DH;
        const float* g = gram_s + h*48;
        float qn = fmaxf(sqrtf(g[36 + d]), EPSN);
        float a[6]; float m = -1e30f;
        #pragma unroll
        for (int e = 0; e < 6; ++e) {
            float kn = fmaxf(sqrtf(g[42 + e]), EPSN);
            a[e] = g[d*6+e] * SCALE / (qn * kn);
            m = fmaxf(m, a[e]);
        }
        float s = 0.f;
        #pragma unroll
        for (int e = 0; e < 6; ++e) { a[e] = expf(a[e]-m); s += a[e]; }
        float inv = 1.f / s;
        #pragma unroll
        for (int e = 0; e < 6; ++e) attn_s[h][d*6+e] = a[e]*inv;
    }
    __syncthreads();

    for (int idx = tid; idx < C*C; idx += blockDim.x) {
        int c = idx / C, c2 = idx % C;
        int h2 = c2 / DH, e = c2 % DH;
        float s = 0.f;
        #pragma unroll
        for (int d = 0; d < 6; ++d)
            s += wproj[c*C + h2*DH + d] * attn_s[h2][d*6+e];
        g_M[b*C*C + idx] = s;
    }
}

/* -------------------- out = M[b] @ v (R2 version, 97us) ----------------- */
__global__ __launch_bounds__(256)
void k_proj(float* __restrict__ out)
{
    int b = blockIdx.y;
    int n = blockIdx.x * 256 + threadIdx.x;
    __shared__ float Ms[C*C];
    for (int i = threadIdx.x; i < C*C; i += 256) Ms[i] = g_M[b*C*C + i];
    __syncthreads();
    float vv[C];
    const float* vp = g_v + (size_t)b*C*NPIX + n;
    #pragma unroll
    for (int c2 = 0; c2 < C; ++c2) vv[c2] = vp[(size_t)c2*NPIX];
    float* op = out + (size_t)b*C*NPIX + n;
    #pragma unroll 4
    for (int c = 0; c < C; ++c) {
        const float4* mr = reinterpret_cast<const float4*>(Ms + c*C);
        float s = 0.f;
        #pragma unroll
        for (int i = 0; i < 12; ++i) {
            float4 w = mr[i];
            s += w.x*vv[4*i] + w.y*vv[4*i+1] + w.z*vv[4*i+2] + w.w*vv[4*i+3];
        }
        op[(size_t)c*NPIX] = s;
    }
}

extern "C" void kernel_launch(void* const* d_in, const int* in_sizes, int n_in,
                              void* d_out, int out_size)
{
    const float* x     = (const float*)d_in[0];
    const float* wqkv  = (const float*)d_in[1];
    const float* wdw   = (const float*)d_in[2];
    const float* wproj = (const float*)d_in[3];
    float* out = (float*)d_out;

    cudaFuncSetAttribute(k_pw, cudaFuncAttributeMaxDynamicSharedMemorySize,
                         PW_SMF * (int)sizeof(float));
    cudaFuncSetAttribute(k_dw32, cudaFuncAttributeMaxDynamicSharedMemorySize,
                         DW_SMF * (int)sizeof(float));

    dim3 gpw(NPIX/PWN, B);
    k_pw<<<gpw, PW_NT, PW_SMF * sizeof(float)>>>(x, wqkv);

    dim3 gdw(WW/TX, HH/TY, B*14);
    k_dw32<<<gdw, DW_NT, DW_SMF * sizeof(float)>>>(wdw);

    k_attn<<<B, 384>>>(wproj);

    dim3 gp(NPIX/256, B);
    k_proj<<<gp, 256>>>(out);
}

// round 9
// speedup vs baseline: 1.8759x; 1.3496x over previous
#include <cuda_runtime.h>
#include <math.h>

#define B 8
#define C 48
#define C3 144
#define HH 256
#define WW 256
#define NPIX (HH*WW)
#define HEADS 8
#define DH 6
#define SCALE 0.40824829046386296f
#define EPSN 1e-12f

/* ---- scratch ---- */
__device__ float g_qkv[(size_t)B*C3*NPIX];
__device__ float g_v[(size_t)B*C*NPIX];
#define NTIL 64         /* 64 row-strips of 4 rows */
__device__ float g_part[B*NTIL*HEADS*48];
__device__ float g_M[B*C*C];

/* ================= k_pw: qkv[144][n] = W[144][48] @ x[48][n] ============ */
#define PWN 128
#define PW_TX 32
#define PW_TY 12
#define PW_NT (PW_TX*PW_TY)    /* 384 */
#define PW_XS 0
#define PW_WT (48*PWN)
#define PW_SMF (48*PWN + 48*C3)   /* 13056 floats = 52224 B */

__global__ __launch_bounds__(PW_NT, 2)
void k_pw(const float* __restrict__ x, const float* __restrict__ wqkv)
{
    extern __shared__ float sm[];
    float* xs = sm + PW_XS;
    float* wT = sm + PW_WT;

    const int tid = threadIdx.x;
    const int tx = tid & 31, ty = tid >> 5;
    const int b = blockIdx.y;
    const int n0 = blockIdx.x * PWN;

    const float* xb = x + (size_t)b*C*NPIX + n0;
    for (int i = tid; i < C*PWN; i += PW_NT)
        xs[i] = xb[(size_t)(i >> 7)*NPIX + (i & 127)];
    for (int i = tid; i < C3*C; i += PW_NT)
        wT[(i % C)*C3 + (i / C)] = wqkv[i];
    __syncthreads();

    float4 acc[12];
    #pragma unroll
    for (int j = 0; j < 12; ++j) acc[j] = make_float4(0.f,0.f,0.f,0.f);

    const float4* xcol = reinterpret_cast<const float4*>(xs) + tx;
    const float*  wrow = wT + ty*12;

    #pragma unroll 4
    for (int cin = 0; cin < C; ++cin) {
        float4 xv = xcol[cin*(PWN/4)];
        const float4* w4 = reinterpret_cast<const float4*>(wrow + cin*C3);
        float4 w0 = w4[0], w1 = w4[1], w2 = w4[2];
        acc[0].x += w0.x*xv.x; acc[0].y += w0.x*xv.y; acc[0].z += w0.x*xv.z; acc[0].w += w0.x*xv.w;
        acc[1].x += w0.y*xv.x; acc[1].y += w0.y*xv.y; acc[1].z += w0.y*xv.z; acc[1].w += w0.y*xv.w;
        acc[2].x += w0.z*xv.x; acc[2].y += w0.z*xv.y; acc[2].z += w0.z*xv.z; acc[2].w += w0.z*xv.w;
        acc[3].x += w0.w*xv.x; acc[3].y += w0.w*xv.y; acc[3].z += w0.w*xv.z; acc[3].w += w0.w*xv.w;
        acc[4].x += w1.x*xv.x; acc[4].y += w1.x*xv.y; acc[4].z += w1.x*xv.z; acc[4].w += w1.x*xv.w;
        acc[5].x += w1.y*xv.x; acc[5].y += w1.y*xv.y; acc[5].z += w1.y*xv.z; acc[5].w += w1.y*xv.w;
        acc[6].x += w1.z*xv.x; acc[6].y += w1.z*xv.y; acc[6].z += w1.z*xv.z; acc[6].w += w1.z*xv.w;
        acc[7].x += w1.w*xv.x; acc[7].y += w1.w*xv.y; acc[7].z += w1.w*xv.z; acc[7].w += w1.w*xv.w;
        acc[8].x += w2.x*xv.x; acc[8].y += w2.x*xv.y; acc[8].z += w2.x*xv.z; acc[8].w += w2.x*xv.w;
        acc[9].x += w2.y*xv.x; acc[9].y += w2.y*xv.y; acc[9].z += w2.y*xv.z; acc[9].w += w2.y*xv.w;
        acc[10].x += w2.z*xv.x; acc[10].y += w2.z*xv.y; acc[10].z += w2.z*xv.z; acc[10].w += w2.z*xv.w;
        acc[11].x += w2.w*xv.x; acc[11].y += w2.w*xv.y; acc[11].z += w2.w*xv.z; acc[11].w += w2.w*xv.w;
    }

    float* ob = g_qkv + (size_t)b*C3*NPIX + n0 + tx*4;
    #pragma unroll
    for (int j = 0; j < 12; ++j) {
        int cout = ty*12 + j;
        *reinterpret_cast<float4*>(ob + (size_t)cout*NPIX) = acc[j];
    }
}

/* ===== k_dws: row-strip depthwise 3x3 + gram partials / v store =====
   block = 512 thr, 4 output rows x 256 cols x 12 channels.
   staging: shifts/masks only, contiguous 1KB-row LDGs. */
#define DR 4                  /* output rows per strip */
#define SR 6                  /* staged rows */
#define DCOL 258              /* 256 + 2 pad */
#define DW_NT 512
/* smem floats: halo 12*6*258=18576, dws 12*1024=12288, wds 108 */
#define DW_HALO 0
#define DW_DWS (12*SR*DCOL)
#define DW_WDS (DW_DWS + 12*DR*256)
#define DW_SMF (DW_WDS + 12*9)        /* 30972 fl = 123888 B */

__device__ __forceinline__ int dw_chan(int g, int j)
{
    /* head group g<8: j<6 -> q chan, else k chan; v group: 96 + (g-8)*12 + j */
    if (g < 8) return (j < 6) ? (g*DH + j) : (C + g*DH + (j - 6));
    return 2*C + (g - 8)*12 + j;
}

__global__ __launch_bounds__(DW_NT, 1)
void k_dws(const float* __restrict__ wdw)
{
    extern __shared__ float sm[];
    float* halo = sm + DW_HALO;
    float* dws  = sm + DW_DWS;
    float* wds  = sm + DW_WDS;

    const int tid = threadIdx.x;
    const int strip = blockIdx.x;   /* 0..63 */
    const int g = blockIdx.y;       /* 0..11 */
    const int b = blockIdx.z;
    const int r0 = strip * DR;
    const bool isHead = (g < 8);

    if (tid < 12*9)
        wds[tid] = wdw[dw_chan(g, tid/9)*9 + tid%9];

    /* stage 12 ch x 6 rows x 256 cols (zero-pad rows outside, pad cols) */
    const float* qb = g_qkv + (size_t)b*C3*NPIX;
    #pragma unroll
    for (int it = 0; it < (12*SR*256)/DW_NT; ++it) {
        int i = it*DW_NT + tid;
        int chrow = i >> 8;            /* 0..71 = ch*6+row */
        int col = i & 255;
        int ch = chrow / SR;           /* const-div, cheap */
        int row = chrow - ch*SR;
        int grow = r0 - 1 + row;
        float v = 0.f;
        if ((unsigned)grow < (unsigned)HH)
            v = qb[(size_t)dw_chan(g, ch)*NPIX + grow*WW + col];
        halo[chrow*DCOL + col + 1] = v;
    }
    if (tid < 12*SR) {
        halo[tid*DCOL] = 0.f;
        halo[tid*DCOL + DCOL - 1] = 0.f;
    }
    __syncthreads();

    const int rh = tid >> 8;          /* 0 or 1 */
    const int col = tid & 255;

    if (isHead) {
        #pragma unroll
        for (int rr = 0; rr < 2; ++rr) {
            const int r = rh*2 + rr;  /* output row 0..3 */
            #pragma unroll
            for (int ch = 0; ch < 12; ++ch) {
                const float* w = wds + ch*9;
                const float* p = halo + (ch*SR + r)*DCOL + col;
                dws[ch*(DR*256) + r*256 + col] =
                      w[0]*p[0]       + w[1]*p[1]        + w[2]*p[2]
                    + w[3]*p[DCOL]    + w[4]*p[DCOL+1]   + w[5]*p[DCOL+2]
                    + w[6]*p[2*DCOL]  + w[7]*p[2*DCOL+1] + w[8]*p[2*DCOL+2];
            }
        }
        __syncthreads();
        const int warp = tid >> 5, lane = tid & 31;
        #pragma unroll
        for (int i = 0; i < 3; ++i) {
            int combo = warp*3 + i;
            const float *pa, *pb;
            if (combo < 36)      { pa = dws + (combo/6)*(DR*256);      pb = dws + (6 + combo%6)*(DR*256); }
            else if (combo < 42) { pa = dws + (combo-36)*(DR*256);     pb = pa; }
            else                 { pa = dws + (6 + combo-42)*(DR*256); pb = pa; }
            float s = 0.f;
            #pragma unroll
            for (int k = 0; k < (DR*256)/32; ++k)
                s += pa[lane + k*32] * pb[lane + k*32];
            #pragma unroll
            for (int off = 16; off; off >>= 1)
                s += __shfl_down_sync(0xffffffffu, s, off);
            if (lane == 0)
                g_part[((size_t)(b*NTIL + strip)*HEADS + g)*48 + combo] = s;
        }
    } else {
        float* vb = g_v + (size_t)b*C*NPIX + (size_t)((g-8)*12)*NPIX;
        #pragma unroll
        for (int rr = 0; rr < 2; ++rr) {
            const int r = rh*2 + rr;
            #pragma unroll
            for (int ch = 0; ch < 12; ++ch) {
                const float* w = wds + ch*9;
                const float* p = halo + (ch*SR + r)*DCOL + col;
                float dv = w[0]*p[0]       + w[1]*p[1]        + w[2]*p[2]
                         + w[3]*p[DCOL]    + w[4]*p[DCOL+1]   + w[5]*p[DCOL+2]
                         + w[6]*p[2*DCOL]  + w[7]*p[2*DCOL+1] + w[8]*p[2*DCOL+2];
                vb[(size_t)ch*NPIX + (r0 + r)*WW + col] = dv;
            }
        }
    }
}

/* ===== reduce partials + softmax + fold attn into M = Wproj*blockdiag ===== */
__global__ __launch_bounds__(384)
void k_attn(const float* __restrict__ wproj)
{
    const int b = blockIdx.x, tid = threadIdx.x;
    __shared__ float gram_s[HEADS*48];
    __shared__ float attn_s[HEADS][36];

    if (tid < HEADS*48) {
        const float* p = g_part + (size_t)b*NTIL*(HEADS*48) + tid;
        float s = 0.f;
        for (int t = 0; t < NTIL; ++t) s += p[(size_t)t*(HEADS*48)];
        gram_s[tid] = s;
    }
    __syncthreads();

    if (tid < HEADS*DH) {
        int h = tid / DH, d = tid % DH;
        const float* g = gram_s + h*48;
        float qn = fmaxf(sqrtf(g[36 + d]), EPSN);
        float a[6]; float m = -1e30f;
        #pragma unroll
        for (int e = 0; e < 6; ++e) {
            float kn = fmaxf(sqrtf(g[42 + e]), EPSN);
            a[e] = g[d*6+e] * SCALE / (qn * kn);
            m = fmaxf(m, a[e]);
        }
        float s = 0.f;
        #pragma unroll
        for (int e = 0; e < 6; ++e) { a[e] = expf(a[e]-m); s += a[e]; }
        float inv = 1.f / s;
        #pragma unroll
        for (int e = 0; e < 6; ++e) attn_s[h][d*6+e] = a[e]*inv;
    }
    __syncthreads();

    for (int idx = tid; idx < C*C; idx += blockDim.x) {
        int c = idx / C, c2 = idx % C;
        int h2 = c2 / DH, e = c2 % DH;
        float s = 0.f;
        #pragma unroll
        for (int d = 0; d < 6; ++d)
            s += wproj[c*C + h2*DH + d] * attn_s[h2][d*6+e];
        g_M[b*C*C + idx] = s;
    }
}

/* -------------------- out = M[b] @ v ------------------------- */
__global__ __launch_bounds__(256)
void k_proj(float* __restrict__ out)
{
    int b = blockIdx.y;
    int n = blockIdx.x * 256 + threadIdx.x;
    __shared__ float Ms[C*C];
    for (int i = threadIdx.x; i < C*C; i += 256) Ms[i] = g_M[b*C*C + i];
    __syncthreads();
    float vv[C];
    const float* vp = g_v + (size_t)b*C*NPIX + n;
    #pragma unroll
    for (int c2 = 0; c2 < C; ++c2) vv[c2] = vp[(size_t)c2*NPIX];
    float* op = out + (size_t)b*C*NPIX + n;
    #pragma unroll 4
    for (int c = 0; c < C; ++c) {
        const float4* mr = reinterpret_cast<const float4*>(Ms + c*C);
        float s = 0.f;
        #pragma unroll
        for (int i = 0; i < 12; ++i) {
            float4 w = mr[i];
            s += w.x*vv[4*i] + w.y*vv[4*i+1] + w.z*vv[4*i+2] + w.w*vv[4*i+3];
        }
        op[(size_t)c*NPIX] = s;
    }
}

extern "C" void kernel_launch(void* const* d_in, const int* in_sizes, int n_in,
                              void* d_out, int out_size)
{
    const float* x     = (const float*)d_in[0];
    const float* wqkv  = (const float*)d_in[1];
    const float* wdw   = (const float*)d_in[2];
    const float* wproj = (const float*)d_in[3];
    float* out = (float*)d_out;

    cudaFuncSetAttribute(k_pw, cudaFuncAttributeMaxDynamicSharedMemorySize,
                         PW_SMF * (int)sizeof(float));
    cudaFuncSetAttribute(k_dws, cudaFuncAttributeMaxDynamicSharedMemorySize,
                         DW_SMF * (int)sizeof(float));

    dim3 gpw(NPIX/PWN, B);
    k_pw<<<gpw, PW_NT, PW_SMF * sizeof(float)>>>(x, wqkv);

    dim3 gdw(NTIL, 12, B);
    k_dws<<<gdw, DW_NT, DW_SMF * sizeof(float)>>>(wdw);

    k_attn<<<B, 384>>>(wproj);

    dim3 gp(NPIX/256, B);
    k_proj<<<gp, 256>>>(out);
}

// round 11
// speedup vs baseline: 1.9910x; 1.0613x over previous
#include <cuda_runtime.h>
#include <math.h>

#define B 8
#define C 48
#define C3 144
#define HH 256
#define WW 256
#define NPIX (HH*WW)
#define HEADS 8
#define DH 6
#define SCALE 0.40824829046386296f
#define EPSN 1e-12f

/* ---- scratch ---- */
__device__ float g_qkv[(size_t)B*C3*NPIX];
#define NTIL 64         /* 64 row-strips of 4 rows (gram kernel) */
__device__ float g_part[B*NTIL*HEADS*48];
__device__ float g_M[B*C*C];

/* ================= k_pw: qkv[144][n] = W[144][48] @ x[48][n] ============ */
#define PWN 128
#define PW_TX 32
#define PW_TY 12
#define PW_NT (PW_TX*PW_TY)    /* 384 */
#define PW_XS 0
#define PW_WT (48*PWN)
#define PW_SMF (48*PWN + 48*C3)   /* 13056 floats = 52224 B */

__global__ __launch_bounds__(PW_NT, 2)
void k_pw(const float* __restrict__ x, const float* __restrict__ wqkv)
{
    extern __shared__ float sm[];
    float* xs = sm + PW_XS;
    float* wT = sm + PW_WT;

    const int tid = threadIdx.x;
    const int tx = tid & 31, ty = tid >> 5;
    const int b = blockIdx.y;
    const int n0 = blockIdx.x * PWN;

    const float* xb = x + (size_t)b*C*NPIX + n0;
    for (int i = tid; i < C*PWN; i += PW_NT)
        xs[i] = xb[(size_t)(i >> 7)*NPIX + (i & 127)];
    for (int i = tid; i < C3*C; i += PW_NT)
        wT[(i % C)*C3 + (i / C)] = wqkv[i];
    __syncthreads();

    float4 acc[12];
    #pragma unroll
    for (int j = 0; j < 12; ++j) acc[j] = make_float4(0.f,0.f,0.f,0.f);

    const float4* xcol = reinterpret_cast<const float4*>(xs) + tx;
    const float*  wrow = wT + ty*12;

    #pragma unroll 4
    for (int cin = 0; cin < C; ++cin) {
        float4 xv = xcol[cin*(PWN/4)];
        const float4* w4 = reinterpret_cast<const float4*>(wrow + cin*C3);
        float4 w0 = w4[0], w1 = w4[1], w2 = w4[2];
        acc[0].x += w0.x*xv.x; acc[0].y += w0.x*xv.y; acc[0].z += w0.x*xv.z; acc[0].w += w0.x*xv.w;
        acc[1].x += w0.y*xv.x; acc[1].y += w0.y*xv.y; acc[1].z += w0.y*xv.z; acc[1].w += w0.y*xv.w;
        acc[2].x += w0.z*xv.x; acc[2].y += w0.z*xv.y; acc[2].z += w0.z*xv.z; acc[2].w += w0.z*xv.w;
        acc[3].x += w0.w*xv.x; acc[3].y += w0.w*xv.y; acc[3].z += w0.w*xv.z; acc[3].w += w0.w*xv.w;
        acc[4].x += w1.x*xv.x; acc[4].y += w1.x*xv.y; acc[4].z += w1.x*xv.z; acc[4].w += w1.x*xv.w;
        acc[5].x += w1.y*xv.x; acc[5].y += w1.y*xv.y; acc[5].z += w1.y*xv.z; acc[5].w += w1.y*xv.w;
        acc[6].x += w1.z*xv.x; acc[6].y += w1.z*xv.y; acc[6].z += w1.z*xv.z; acc[6].w += w1.z*xv.w;
        acc[7].x += w1.w*xv.x; acc[7].y += w1.w*xv.y; acc[7].z += w1.w*xv.z; acc[7].w += w1.w*xv.w;
        acc[8].x += w2.x*xv.x; acc[8].y += w2.x*xv.y; acc[8].z += w2.x*xv.z; acc[8].w += w2.x*xv.w;
        acc[9].x += w2.y*xv.x; acc[9].y += w2.y*xv.y; acc[9].z += w2.y*xv.z; acc[9].w += w2.y*xv.w;
        acc[10].x += w2.z*xv.x; acc[10].y += w2.z*xv.y; acc[10].z += w2.z*xv.z; acc[10].w += w2.z*xv.w;
        acc[11].x += w2.w*xv.x; acc[11].y += w2.w*xv.y; acc[11].z += w2.w*xv.z; acc[11].w += w2.w*xv.w;
    }

    float* ob = g_qkv + (size_t)b*C3*NPIX + n0 + tx*4;
    #pragma unroll
    for (int j = 0; j < 12; ++j) {
        int cout = ty*12 + j;
        *reinterpret_cast<float4*>(ob + (size_t)cout*NPIX) = acc[j];
    }
}

/* ===== k_dwg: row-strip depthwise 3x3 on q,k + gram partials =====
   block = 512 thr, 4 output rows x 256 cols x 12 channels (6 q + 6 k). */
#define DR 4
#define SR 6
#define DCOL 258
#define DW_NT 512
#define DW_HALO 0
#define DW_DWS (12*SR*DCOL)
#define DW_WDS (DW_DWS + 12*DR*256)
#define DW_SMF (DW_WDS + 12*9)        /* 30972 fl = 123888 B */

__device__ __forceinline__ int hk_chan(int g, int j)
{
    return (j < 6) ? (g*DH + j) : (C + g*DH + (j - 6));
}

__global__ __launch_bounds__(DW_NT, 1)
void k_dwg(const float* __restrict__ wdw)
{
    extern __shared__ float sm[];
    float* halo = sm + DW_HALO;
    float* dws  = sm + DW_DWS;
    float* wds  = sm + DW_WDS;

    const int tid = threadIdx.x;
    const int strip = blockIdx.x;   /* 0..63 */
    const int g = blockIdx.y;       /* head 0..7 */
    const int b = blockIdx.z;
    const int r0 = strip * DR;

    if (tid < 12*9)
        wds[tid] = wdw[hk_chan(g, tid/9)*9 + tid%9];

    const float* qb = g_qkv + (size_t)b*C3*NPIX;
    #pragma unroll
    for (int it = 0; it < (12*SR*256)/DW_NT; ++it) {
        int i = it*DW_NT + tid;
        int chrow = i >> 8;
        int col = i & 255;
        int ch = chrow / SR;
        int row = chrow - ch*SR;
        int grow = r0 - 1 + row;
        float v = 0.f;
        if ((unsigned)grow < (unsigned)HH)
            v = qb[(size_t)hk_chan(g, ch)*NPIX + grow*WW + col];
        halo[chrow*DCOL + col + 1] = v;
    }
    if (tid < 12*SR) {
        halo[tid*DCOL] = 0.f;
        halo[tid*DCOL + DCOL - 1] = 0.f;
    }
    __syncthreads();

    const int rh = tid >> 8;
    const int col = tid & 255;

    #pragma unroll
    for (int rr = 0; rr < 2; ++rr) {
        const int r = rh*2 + rr;
        #pragma unroll
        for (int ch = 0; ch < 12; ++ch) {
            const float* w = wds + ch*9;
            const float* p = halo + (ch*SR + r)*DCOL + col;
            dws[ch*(DR*256) + r*256 + col] =
                  w[0]*p[0]       + w[1]*p[1]        + w[2]*p[2]
                + w[3]*p[DCOL]    + w[4]*p[DCOL+1]   + w[5]*p[DCOL+2]
                + w[6]*p[2*DCOL]  + w[7]*p[2*DCOL+1] + w[8]*p[2*DCOL+2];
        }
    }
    __syncthreads();
    const int warp = tid >> 5, lane = tid & 31;
    #pragma unroll
    for (int i = 0; i < 3; ++i) {
        int combo = warp*3 + i;
        const float *pa, *pb;
        if (combo < 36)      { pa = dws + (combo/6)*(DR*256);      pb = dws + (6 + combo%6)*(DR*256); }
        else if (combo < 42) { pa = dws + (combo-36)*(DR*256);     pb = pa; }
        else                 { pa = dws + (6 + combo-42)*(DR*256); pb = pa; }
        float s = 0.f;
        #pragma unroll
        for (int k = 0; k < (DR*256)/32; ++k)
            s += pa[lane + k*32] * pb[lane + k*32];
        #pragma unroll
        for (int off = 16; off; off >>= 1)
            s += __shfl_down_sync(0xffffffffu, s, off);
        if (lane == 0)
            g_part[((size_t)(b*NTIL + strip)*HEADS + g)*48 + combo] = s;
    }
}

/* ===== reduce partials + softmax + fold attn into M = Wproj*blockdiag ===== */
__global__ __launch_bounds__(384)
void k_attn(const float* __restrict__ wproj)
{
    const int b = blockIdx.x, tid = threadIdx.x;
    __shared__ float gram_s[HEADS*48];
    __shared__ float attn_s[HEADS][36];

    if (tid < HEADS*48) {
        const float* p = g_part + (size_t)b*NTIL*(HEADS*48) + tid;
        float s = 0.f;
        for (int t = 0; t < NTIL; ++t) s += p[(size_t)t*(HEADS*48)];
        gram_s[tid] = s;
    }
    __syncthreads();

    if (tid < HEADS*DH) {
        int h = tid / DH, d = tid % DH;
        const float* g = gram_s + h*48;
        float qn = fmaxf(sqrtf(g[36 + d]), EPSN);
        float a[6]; float m = -1e30f;
        #pragma unroll
        for (int e = 0; e < 6; ++e) {
            float kn = fmaxf(sqrtf(g[42 + e]), EPSN);
            a[e] = g[d*6+e] * SCALE / (qn * kn);
            m = fmaxf(m, a[e]);
        }
        float s = 0.f;
        #pragma unroll
        for (int e = 0; e < 6; ++e) { a[e] = expf(a[e]-m); s += a[e]; }
        float inv = 1.f / s;
        #pragma unroll
        for (int e = 0; e < 6; ++e) attn_s[h][d*6+e] = a[e]*inv;
    }
    __syncthreads();

    for (int idx = tid; idx < C*C; idx += blockDim.x) {
        int c = idx / C, c2 = idx % C;
        int h2 = c2 / DH, e = c2 % DH;
        float s = 0.f;
        #pragma unroll
        for (int d = 0; d < 6; ++d)
            s += wproj[c*C + h2*DH + d] * attn_s[h2][d*6+e];
        g_M[b*C*C + idx] = s;
    }
}

/* ===== k_vproj: fused depthwise(v) + out = M @ dv, direct to output =====
   block = 512 thr = 2 output rows x 256 cols; stages 48 v channels x 4 rows. */
#define VR 2
#define VSR 4
#define VCOL 258
#define VP_NT 512
#define VP_HALO 0
#define VP_MS (C*VSR*VCOL)            /* 49536 */
#define VP_WDS (VP_MS + C*C)          /* +2304 */
#define VP_SMF (VP_WDS + C*9)         /* 52272 fl = 209088 B */

__global__ __launch_bounds__(VP_NT, 1)
void k_vproj(const float* __restrict__ wdw, float* __restrict__ out)
{
    extern __shared__ float sm[];
    float* halo = sm + VP_HALO;
    float* Ms   = sm + VP_MS;
    float* wds  = sm + VP_WDS;

    const int tid = threadIdx.x;
    const int strip = blockIdx.x;   /* 0..127 */
    const int b = blockIdx.y;
    const int r0 = strip * VR;

    if (tid < C*9)
        wds[tid] = wdw[(2*C + tid/9)*9 + tid%9];
    for (int i = tid; i < C*C; i += VP_NT)
        Ms[i] = g_M[b*C*C + i];

    /* stage 48 v channels x 4 rows x 256 cols */
    const float* qb = g_qkv + (size_t)b*C3*NPIX + (size_t)(2*C)*NPIX;
    #pragma unroll
    for (int it = 0; it < (C*VSR*256)/VP_NT; ++it) {
        int i = it*VP_NT + tid;
        int chrow = i >> 8;            /* 0..191 = ch*4+row */
        int col = i & 255;
        int ch = chrow >> 2;
        int row = chrow & 3;
        int grow = r0 - 1 + row;
        float v = 0.f;
        if ((unsigned)grow < (unsigned)HH)
            v = qb[(size_t)ch*NPIX + grow*WW + col];
        halo[chrow*VCOL + col + 1] = v;
    }
    if (tid < C*VSR) {
        halo[tid*VCOL] = 0.f;
        halo[tid*VCOL + VCOL - 1] = 0.f;
    }
    __syncthreads();

    const int rh = tid >> 8;           /* output row within strip: 0/1 */
    const int col = tid & 255;

    /* depthwise for all 48 v channels at this pixel */
    float dv[C];
    #pragma unroll
    for (int ch = 0; ch < C; ++ch) {
        const float* w = wds + ch*9;
        const float* p = halo + (ch*VSR + rh)*VCOL + col;
        dv[ch] = w[0]*p[0]       + w[1]*p[1]        + w[2]*p[2]
               + w[3]*p[VCOL]    + w[4]*p[VCOL+1]   + w[5]*p[VCOL+2]
               + w[6]*p[2*VCOL]  + w[7]*p[2*VCOL+1] + w[8]*p[2*VCOL+2];
    }

    /* out[c] = M[c] . dv */
    float* op = out + (size_t)b*C*NPIX + (r0 + rh)*WW + col;
    #pragma unroll 4
    for (int c = 0; c < C; ++c) {
        const float4* mr = reinterpret_cast<const float4*>(Ms + c*C);
        float s = 0.f;
        #pragma unroll
        for (int i = 0; i < 12; ++i) {
            float4 w = mr[i];
            s += w.x*dv[4*i] + w.y*dv[4*i+1] + w.z*dv[4*i+2] + w.w*dv[4*i+3];
        }
        op[(size_t)c*NPIX] = s;
    }
}

extern "C" void kernel_launch(void* const* d_in, const int* in_sizes, int n_in,
                              void* d_out, int out_size)
{
    const float* x     = (const float*)d_in[0];
    const float* wqkv  = (const float*)d_in[1];
    const float* wdw   = (const float*)d_in[2];
    const float* wproj = (const float*)d_in[3];
    float* out = (float*)d_out;

    cudaFuncSetAttribute(k_pw, cudaFuncAttributeMaxDynamicSharedMemorySize,
                         PW_SMF * (int)sizeof(float));
    cudaFuncSetAttribute(k_dwg, cudaFuncAttributeMaxDynamicSharedMemorySize,
                         DW_SMF * (int)sizeof(float));
    cudaFuncSetAttribute(k_vproj, cudaFuncAttributeMaxDynamicSharedMemorySize,
                         VP_SMF * (int)sizeof(float));

    dim3 gpw(NPIX/PWN, B);
    k_pw<<<gpw, PW_NT, PW_SMF * sizeof(float)>>>(x, wqkv);

    dim3 gdw(NTIL, HEADS, B);
    k_dwg<<<gdw, DW_NT, DW_SMF * sizeof(float)>>>(wdw);

    k_attn<<<B, 384>>>(wproj);

    dim3 gvp(HH/VR, B);
    k_vproj<<<gvp, VP_NT, VP_SMF * sizeof(float)>>>(wdw, out);
}

// round 16
// speedup vs baseline: 2.0819x; 1.0456x over previous
#include <cuda_runtime.h>
#include <math.h>

#define B 8
#define C 48
#define C3 144
#define HH 256
#define WW 256
#define NPIX (HH*WW)
#define HEADS 8
#define DH 6
#define SCALE 0.40824829046386296f
#define EPSN 1e-12f

/* ---- scratch ---- */
__device__ float g_qkv[(size_t)B*C3*NPIX];
#define NTIL 64         /* 64 row-strips of 4 rows (gram kernel) */
__device__ float g_part[B*NTIL*HEADS*48];
__device__ float g_M[B*C*C];

/* ================= k_pw: qkv[144][n] = W[144][48] @ x[48][n] ============ */
#define PWN 128
#define PW_TX 32
#define PW_TY 12
#define PW_NT (PW_TX*PW_TY)    /* 384 */
#define PW_XS 0
#define PW_WT (48*PWN)
#define PW_SMF (48*PWN + 48*C3)   /* 13056 floats = 52224 B */

__global__ __launch_bounds__(PW_NT, 2)
void k_pw(const float* __restrict__ x, const float* __restrict__ wqkv)
{
    extern __shared__ float sm[];
    float* xs = sm + PW_XS;
    float* wT = sm + PW_WT;

    const int tid = threadIdx.x;
    const int tx = tid & 31, ty = tid >> 5;
    const int b = blockIdx.y;
    const int n0 = blockIdx.x * PWN;

    const float* xb = x + (size_t)b*C*NPIX + n0;
    for (int i = tid; i < C*PWN; i += PW_NT)
        xs[i] = xb[(size_t)(i >> 7)*NPIX + (i & 127)];
    for (int i = tid; i < C3*C; i += PW_NT)
        wT[(i % C)*C3 + (i / C)] = wqkv[i];
    __syncthreads();

    float4 acc[12];
    #pragma unroll
    for (int j = 0; j < 12; ++j) acc[j] = make_float4(0.f,0.f,0.f,0.f);

    const float4* xcol = reinterpret_cast<const float4*>(xs) + tx;
    const float*  wrow = wT + ty*12;

    #pragma unroll 4
    for (int cin = 0; cin < C; ++cin) {
        float4 xv = xcol[cin*(PWN/4)];
        const float4* w4 = reinterpret_cast<const float4*>(wrow + cin*C3);
        float4 w0 = w4[0], w1 = w4[1], w2 = w4[2];
        acc[0].x += w0.x*xv.x; acc[0].y += w0.x*xv.y; acc[0].z += w0.x*xv.z; acc[0].w += w0.x*xv.w;
        acc[1].x += w0.y*xv.x; acc[1].y += w0.y*xv.y; acc[1].z += w0.y*xv.z; acc[1].w += w0.y*xv.w;
        acc[2].x += w0.z*xv.x; acc[2].y += w0.z*xv.y; acc[2].z += w0.z*xv.z; acc[2].w += w0.z*xv.w;
        acc[3].x += w0.w*xv.x; acc[3].y += w0.w*xv.y; acc[3].z += w0.w*xv.z; acc[3].w += w0.w*xv.w;
        acc[4].x += w1.x*xv.x; acc[4].y += w1.x*xv.y; acc[4].z += w1.x*xv.z; acc[4].w += w1.x*xv.w;
        acc[5].x += w1.y*xv.x; acc[5].y += w1.y*xv.y; acc[5].z += w1.y*xv.z; acc[5].w += w1.y*xv.w;
        acc[6].x += w1.z*xv.x; acc[6].y += w1.z*xv.y; acc[6].z += w1.z*xv.z; acc[6].w += w1.z*xv.w;
        acc[7].x += w1.w*xv.x; acc[7].y += w1.w*xv.y; acc[7].z += w1.w*xv.z; acc[7].w += w1.w*xv.w;
        acc[8].x += w2.x*xv.x; acc[8].y += w2.x*xv.y; acc[8].z += w2.x*xv.z; acc[8].w += w2.x*xv.w;
        acc[9].x += w2.y*xv.x; acc[9].y += w2.y*xv.y; acc[9].z += w2.y*xv.z; acc[9].w += w2.y*xv.w;
        acc[10].x += w2.z*xv.x; acc[10].y += w2.z*xv.y; acc[10].z += w2.z*xv.z; acc[10].w += w2.z*xv.w;
        acc[11].x += w2.w*xv.x; acc[11].y += w2.w*xv.y; acc[11].z += w2.w*xv.z; acc[11].w += w2.w*xv.w;
    }

    float* ob = g_qkv + (size_t)b*C3*NPIX + n0 + tx*4;
    #pragma unroll
    for (int j = 0; j < 12; ++j) {
        int cout = ty*12 + j;
        *reinterpret_cast<float4*>(ob + (size_t)cout*NPIX) = acc[j];
    }
}

/* ===== k_dwg: row-strip depthwise 3x3 on q,k + gram partials =====
   block = 512 thr, 4 output rows x 256 cols x 12 channels (6 q + 6 k).
   2-pass dws (rows 0-1 then 2-3) -> smem 99312 B -> 2 CTAs/SM. */
#define DR 4
#define SR 6
#define DCOL 258
#define DW_NT 512
#define DW_HALO 0
#define DW_DWS (12*SR*DCOL)               /* 18576 */
#define DW_WDS (DW_DWS + 12*2*256)        /* +6144 */
#define DW_SMF (DW_WDS + 12*9)            /* 24828 fl = 99312 B */

__device__ __forceinline__ int hk_chan(int g, int j)
{
    return (j < 6) ? (g*DH + j) : (C + g*DH + (j - 6));
}

__global__ __launch_bounds__(DW_NT, 2)
void k_dwg(const float* __restrict__ wdw)
{
    extern __shared__ float sm[];
    float* halo = sm + DW_HALO;
    float* dws  = sm + DW_DWS;     /* 12 ch x 512 px (2 rows) */
    float* wds  = sm + DW_WDS;

    const int tid = threadIdx.x;
    const int strip = blockIdx.x;   /* 0..63 */
    const int g = blockIdx.y;       /* head 0..7 */
    const int b = blockIdx.z;
    const int r0 = strip * DR;

    if (tid < 12*9)
        wds[tid] = wdw[hk_chan(g, tid/9)*9 + tid%9];

    const float* qb = g_qkv + (size_t)b*C3*NPIX;
    #pragma unroll
    for (int it = 0; it < (12*SR*256)/DW_NT; ++it) {
        int i = it*DW_NT + tid;
        int chrow = i >> 8;
        int col = i & 255;
        int ch = chrow / SR;
        int row = chrow - ch*SR;
        int grow = r0 - 1 + row;
        float v = 0.f;
        if ((unsigned)grow < (unsigned)HH)
            v = qb[(size_t)hk_chan(g, ch)*NPIX + grow*WW + col];
        halo[chrow*DCOL + col + 1] = v;
    }
    if (tid < 12*SR) {
        halo[tid*DCOL] = 0.f;
        halo[tid*DCOL + DCOL - 1] = 0.f;
    }
    __syncthreads();

    const int rh = tid >> 8;          /* 0/1: which row of the 2-row pass */
    const int col = tid & 255;
    const int warp = tid >> 5, lane = tid & 31;

    float s3[3] = {0.f, 0.f, 0.f};

    #pragma unroll
    for (int pass = 0; pass < 2; ++pass) {
        const int r = pass*2 + rh;    /* output row 0..3 */
        #pragma unroll
        for (int ch = 0; ch < 12; ++ch) {
            const float* w = wds + ch*9;
            const float* p = halo + (ch*SR + r)*DCOL + col;
            dws[ch*512 + rh*256 + col] =
                  w[0]*p[0]       + w[1]*p[1]        + w[2]*p[2]
                + w[3]*p[DCOL]    + w[4]*p[DCOL+1]   + w[5]*p[DCOL+2]
                + w[6]*p[2*DCOL]  + w[7]*p[2*DCOL+1] + w[8]*p[2*DCOL+2];
        }
        __syncthreads();
        #pragma unroll
        for (int i = 0; i < 3; ++i) {
            int combo = warp*3 + i;
            const float *pa, *pb;
            if (combo < 36)      { pa = dws + (combo/6)*512;      pb = dws + (6 + combo%6)*512; }
            else if (combo < 42) { pa = dws + (combo-36)*512;     pb = pa; }
            else                 { pa = dws + (6 + combo-42)*512; pb = pa; }
            float s = 0.f;
            #pragma unroll
            for (int k = 0; k < 512/32; ++k)
                s += pa[lane + k*32] * pb[lane + k*32];
            s3[i] += s;
        }
        if (pass == 0) __syncthreads();   /* gram reads done before pass-2 writes */
    }

    #pragma unroll
    for (int i = 0; i < 3; ++i) {
        float s = s3[i];
        #pragma unroll
        for (int off = 16; off; off >>= 1)
            s += __shfl_down_sync(0xffffffffu, s, off);
        if (lane == 0)
            g_part[((size_t)(b*NTIL + strip)*HEADS + g)*48 + warp*3 + i] = s;
    }
}

/* ===== reduce partials + softmax + fold attn into M = Wproj*blockdiag ===== */
__global__ __launch_bounds__(384)
void k_attn(const float* __restrict__ wproj)
{
    const int b = blockIdx.x, tid = threadIdx.x;
    __shared__ float gram_s[HEADS*48];
    __shared__ float attn_s[HEADS][36];

    if (tid < HEADS*48) {
        const float* p = g_part + (size_t)b*NTIL*(HEADS*48) + tid;
        float s = 0.f;
        for (int t = 0; t < NTIL; ++t) s += p[(size_t)t*(HEADS*48)];
        gram_s[tid] = s;
    }
    __syncthreads();

    if (tid < HEADS*DH) {
        int h = tid / DH, d = tid % DH;
        const float* g = gram_s + h*48;
        float qn = fmaxf(sqrtf(g[36 + d]), EPSN);
        float a[6]; float m = -1e30f;
        #pragma unroll
        for (int e = 0; e < 6; ++e) {
            float kn = fmaxf(sqrtf(g[42 + e]), EPSN);
            a[e] = g[d*6+e] * SCALE / (qn * kn);
            m = fmaxf(m, a[e]);
        }
        float s = 0.f;
        #pragma unroll
        for (int e = 0; e < 6; ++e) { a[e] = expf(a[e]-m); s += a[e]; }
        float inv = 1.f / s;
        #pragma unroll
        for (int e = 0; e < 6; ++e) attn_s[h][d*6+e] = a[e]*inv;
    }
    __syncthreads();

    for (int idx = tid; idx < C*C; idx += blockDim.x) {
        int c = idx / C, c2 = idx % C;
        int h2 = c2 / DH, e = c2 % DH;
        float s = 0.f;
        #pragma unroll
        for (int d = 0; d < 6; ++d)
            s += wproj[c*C + h2*DH + d] * attn_s[h2][d*6+e];
        g_M[b*C*C + idx] = s;
    }
}

/* ===== k_vproj: fused depthwise(v) + out = M @ dv, direct to output =====
   block = 512 thr = 2 output rows x 256 cols; stages 48 v channels x 4 rows. */
#define VR 2
#define VSR 4
#define VCOL 258
#define VP_NT 512
#define VP_HALO 0
#define VP_MS (C*VSR*VCOL)            /* 49536 */
#define VP_WDS (VP_MS + C*C)          /* +2304 */
#define VP_SMF (VP_WDS + C*9)         /* 52272 fl = 209088 B */

__global__ __launch_bounds__(VP_NT, 1)
void k_vproj(const float* __restrict__ wdw, float* __restrict__ out)
{
    extern __shared__ float sm[];
    float* halo = sm + VP_HALO;
    float* Ms   = sm + VP_MS;
    float* wds  = sm + VP_WDS;

    const int tid = threadIdx.x;
    const int strip = blockIdx.x;   /* 0..127 */
    const int b = blockIdx.y;
    const int r0 = strip * VR;

    if (tid < C*9)
        wds[tid] = wdw[(2*C + tid/9)*9 + tid%9];
    for (int i = tid; i < C*C; i += VP_NT)
        Ms[i] = g_M[b*C*C + i];

    const float* qb = g_qkv + (size_t)b*C3*NPIX + (size_t)(2*C)*NPIX;
    #pragma unroll
    for (int it = 0; it < (C*VSR*256)/VP_NT; ++it) {
        int i = it*VP_NT + tid;
        int chrow = i >> 8;
        int col = i & 255;
        int ch = chrow >> 2;
        int row = chrow & 3;
        int grow = r0 - 1 + row;
        float v = 0.f;
        if ((unsigned)grow < (unsigned)HH)
            v = qb[(size_t)ch*NPIX + grow*WW + col];
        halo[chrow*VCOL + col + 1] = v;
    }
    if (tid < C*VSR) {
        halo[tid*VCOL] = 0.f;
        halo[tid*VCOL + VCOL - 1] = 0.f;
    }
    __syncthreads();

    const int rh = tid >> 8;
    const int col = tid & 255;

    float dv[C];
    #pragma unroll
    for (int ch = 0; ch < C; ++ch) {
        const float* w = wds + ch*9;
        const float* p = halo + (ch*VSR + rh)*VCOL + col;
        dv[ch] = w[0]*p[0]       + w[1]*p[1]        + w[2]*p[2]
               + w[3]*p[VCOL]    + w[4]*p[VCOL+1]   + w[5]*p[VCOL+2]
               + w[6]*p[2*VCOL]  + w[7]*p[2*VCOL+1] + w[8]*p[2*VCOL+2];
    }

    float* op = out + (size_t)b*C*NPIX + (r0 + rh)*WW + col;
    #pragma unroll 4
    for (int c = 0; c < C; ++c) {
        const float4* mr = reinterpret_cast<const float4*>(Ms + c*C);
        float s = 0.f;
        #pragma unroll
        for (int i = 0; i < 12; ++i) {
            float4 w = mr[i];
            s += w.x*dv[4*i] + w.y*dv[4*i+1] + w.z*dv[4*i+2] + w.w*dv[4*i+3];
        }
        op[(size_t)c*NPIX] = s;
    }
}

extern "C" void kernel_launch(void* const* d_in, const int* in_sizes, int n_in,
                              void* d_out, int out_size)
{
    const float* x     = (const float*)d_in[0];
    const float* wqkv  = (const float*)d_in[1];
    const float* wdw   = (const float*)d_in[2];
    const float* wproj = (const float*)d_in[3];
    float* out = (float*)d_out;

    cudaFuncSetAttribute(k_pw, cudaFuncAttributeMaxDynamicSharedMemorySize,
                         PW_SMF * (int)sizeof(float));
    cudaFuncSetAttribute(k_dwg, cudaFuncAttributeMaxDynamicSharedMemorySize,
                         DW_SMF * (int)sizeof(float));
    cudaFuncSetAttribute(k_vproj, cudaFuncAttributeMaxDynamicSharedMemorySize,
                         VP_SMF * (int)sizeof(float));

    dim3 gpw(NPIX/PWN, B);
    k_pw<<<gpw, PW_NT, PW_SMF * sizeof(float)>>>(x, wqkv);

    dim3 gdw(NTIL, HEADS, B);
    k_dwg<<<gdw, DW_NT, DW_SMF * sizeof(float)>>>(wdw);

    k_attn<<<B, 384>>>(wproj);

    dim3 gvp(HH/VR, B);
    k_vproj<<<gvp, VP_NT, VP_SMF * sizeof(float)>>>(wdw, out);
}

// round 17
// speedup vs baseline: 2.1410x; 1.0284x over previous
#include <cuda_runtime.h>
#include <math.h>

#define B 8
#define C 48
#define C3 144
#define HH 256
#define WW 256
#define NPIX (HH*WW)
#define HEADS 8
#define DH 6
#define SCALE 0.40824829046386296f
#define EPSN 1e-12f

/* ---- scratch ---- */
__device__ float g_qkv[(size_t)B*C3*NPIX];
#define NTIL 64
__device__ float g_part[B*NTIL*HEADS*48];
__device__ float g_M[B*C*C];

/* ================= k_pw: qkv[144][n] = W[144][48] @ x[48][n] ============ */
#define PWN 128
#define PW_TX 32
#define PW_TY 12
#define PW_NT (PW_TX*PW_TY)    /* 384 */
#define PW_XS 0
#define PW_WT (48*PWN)
#define PW_SMF (48*PWN + 48*C3)   /* 13056 floats = 52224 B */

__global__ __launch_bounds__(PW_NT, 2)
void k_pw(const float* __restrict__ x, const float* __restrict__ wqkv)
{
    extern __shared__ float sm[];
    float* xs = sm + PW_XS;
    float* wT = sm + PW_WT;

    const int tid = threadIdx.x;
    const int tx = tid & 31, ty = tid >> 5;
    const int b = blockIdx.y;
    const int n0 = blockIdx.x * PWN;

    const float* xb = x + (size_t)b*C*NPIX + n0;
    for (int i = tid; i < C*PWN; i += PW_NT)
        xs[i] = xb[(size_t)(i >> 7)*NPIX + (i & 127)];
    for (int i = tid; i < C3*C; i += PW_NT)
        wT[(i % C)*C3 + (i / C)] = wqkv[i];
    __syncthreads();

    float4 acc[12];
    #pragma unroll
    for (int j = 0; j < 12; ++j) acc[j] = make_float4(0.f,0.f,0.f,0.f);

    const float4* xcol = reinterpret_cast<const float4*>(xs) + tx;
    const float*  wrow = wT + ty*12;

    #pragma unroll 4
    for (int cin = 0; cin < C; ++cin) {
        float4 xv = xcol[cin*(PWN/4)];
        const float4* w4 = reinterpret_cast<const float4*>(wrow + cin*C3);
        float4 w0 = w4[0], w1 = w4[1], w2 = w4[2];
        acc[0].x += w0.x*xv.x; acc[0].y += w0.x*xv.y; acc[0].z += w0.x*xv.z; acc[0].w += w0.x*xv.w;
        acc[1].x += w0.y*xv.x; acc[1].y += w0.y*xv.y; acc[1].z += w0.y*xv.z; acc[1].w += w0.y*xv.w;
        acc[2].x += w0.z*xv.x; acc[2].y += w0.z*xv.y; acc[2].z += w0.z*xv.z; acc[2].w += w0.z*xv.w;
        acc[3].x += w0.w*xv.x; acc[3].y += w0.w*xv.y; acc[3].z += w0.w*xv.z; acc[3].w += w0.w*xv.w;
        acc[4].x += w1.x*xv.x; acc[4].y += w1.x*xv.y; acc[4].z += w1.x*xv.z; acc[4].w += w1.x*xv.w;
        acc[5].x += w1.y*xv.x; acc[5].y += w1.y*xv.y; acc[5].z += w1.y*xv.z; acc[5].w += w1.y*xv.w;
        acc[6].x += w1.z*xv.x; acc[6].y += w1.z*xv.y; acc[6].z += w1.z*xv.z; acc[6].w += w1.z*xv.w;
        acc[7].x += w1.w*xv.x; acc[7].y += w1.w*xv.y; acc[7].z += w1.w*xv.z; acc[7].w += w1.w*xv.w;
        acc[8].x += w2.x*xv.x; acc[8].y += w2.x*xv.y; acc[8].z += w2.x*xv.z; acc[8].w += w2.x*xv.w;
        acc[9].x += w2.y*xv.x; acc[9].y += w2.y*xv.y; acc[9].z += w2.y*xv.z; acc[9].w += w2.y*xv.w;
        acc[10].x += w2.z*xv.x; acc[10].y += w2.z*xv.y; acc[10].z += w2.z*xv.z; acc[10].w += w2.z*xv.w;
        acc[11].x += w2.w*xv.x; acc[11].y += w2.w*xv.y; acc[11].z += w2.w*xv.z; acc[11].w += w2.w*xv.w;
    }

    float* ob = g_qkv + (size_t)b*C3*NPIX + n0 + tx*4;
    #pragma unroll
    for (int j = 0; j < 12; ++j) {
        int cout = ty*12 + j;
        *reinterpret_cast<float4*>(ob + (size_t)cout*NPIX) = acc[j];
    }
}

/* ===== k_dwg: row-strip depthwise 3x3 on q,k + gram partials (2-pass) ===== */
#define DR 4
#define SR 6
#define DCOL 258
#define DW_NT 512
#define DW_HALO 0
#define DW_DWS (12*SR*DCOL)               /* 18576 */
#define DW_WDS (DW_DWS + 12*2*256)        /* +6144 */
#define DW_SMF (DW_WDS + 12*9)            /* 24828 fl = 99312 B */

__device__ __forceinline__ int hk_chan(int g, int j)
{
    return (j < 6) ? (g*DH + j) : (C + g*DH + (j - 6));
}

__global__ __launch_bounds__(DW_NT, 2)
void k_dwg(const float* __restrict__ wdw)
{
    extern __shared__ float sm[];
    float* halo = sm + DW_HALO;
    float* dws  = sm + DW_DWS;
    float* wds  = sm + DW_WDS;

    const int tid = threadIdx.x;
    const int strip = blockIdx.x;
    const int g = blockIdx.y;
    const int b = blockIdx.z;
    const int r0 = strip * DR;

    if (tid < 12*9)
        wds[tid] = wdw[hk_chan(g, tid/9)*9 + tid%9];

    const float* qb = g_qkv + (size_t)b*C3*NPIX;
    #pragma unroll
    for (int it = 0; it < (12*SR*256)/DW_NT; ++it) {
        int i = it*DW_NT + tid;
        int chrow = i >> 8;
        int col = i & 255;
        int ch = chrow / SR;
        int row = chrow - ch*SR;
        int grow = r0 - 1 + row;
        float v = 0.f;
        if ((unsigned)grow < (unsigned)HH)
            v = qb[(size_t)hk_chan(g, ch)*NPIX + grow*WW + col];
        halo[chrow*DCOL + col + 1] = v;
    }
    if (tid < 12*SR) {
        halo[tid*DCOL] = 0.f;
        halo[tid*DCOL + DCOL - 1] = 0.f;
    }
    __syncthreads();

    const int rh = tid >> 8;
    const int col = tid & 255;
    const int warp = tid >> 5, lane = tid & 31;

    float s3[3] = {0.f, 0.f, 0.f};

    #pragma unroll
    for (int pass = 0; pass < 2; ++pass) {
        const int r = pass*2 + rh;
        #pragma unroll
        for (int ch = 0; ch < 12; ++ch) {
            const float* w = wds + ch*9;
            const float* p = halo + (ch*SR + r)*DCOL + col;
            dws[ch*512 + rh*256 + col] =
                  w[0]*p[0]       + w[1]*p[1]        + w[2]*p[2]
                + w[3]*p[DCOL]    + w[4]*p[DCOL+1]   + w[5]*p[DCOL+2]
                + w[6]*p[2*DCOL]  + w[7]*p[2*DCOL+1] + w[8]*p[2*DCOL+2];
        }
        __syncthreads();
        #pragma unroll
        for (int i = 0; i < 3; ++i) {
            int combo = warp*3 + i;
            const float *pa, *pb;
            if (combo < 36)      { pa = dws + (combo/6)*512;      pb = dws + (6 + combo%6)*512; }
            else if (combo < 42) { pa = dws + (combo-36)*512;     pb = pa; }
            else                 { pa = dws + (6 + combo-42)*512; pb = pa; }
            float s = 0.f;
            #pragma unroll
            for (int k = 0; k < 512/32; ++k)
                s += pa[lane + k*32] * pb[lane + k*32];
            s3[i] += s;
        }
        if (pass == 0) __syncthreads();
    }

    #pragma unroll
    for (int i = 0; i < 3; ++i) {
        float s = s3[i];
        #pragma unroll
        for (int off = 16; off; off >>= 1)
            s += __shfl_down_sync(0xffffffffu, s, off);
        if (lane == 0)
            g_part[((size_t)(b*NTIL + strip)*HEADS + g)*48 + warp*3 + i] = s;
    }
}

/* ===== reduce partials + softmax + fold attn into M = Wproj*blockdiag ===== */
__global__ __launch_bounds__(384)
void k_attn(const float* __restrict__ wproj)
{
    const int b = blockIdx.x, tid = threadIdx.x;
    __shared__ float gram_s[HEADS*48];
    __shared__ float attn_s[HEADS][36];

    if (tid < HEADS*48) {
        const float* p = g_part + (size_t)b*NTIL*(HEADS*48) + tid;
        float s = 0.f;
        for (int t = 0; t < NTIL; ++t) s += p[(size_t)t*(HEADS*48)];
        gram_s[tid] = s;
    }
    __syncthreads();

    if (tid < HEADS*DH) {
        int h = tid / DH, d = tid % DH;
        const float* g = gram_s + h*48;
        float qn = fmaxf(sqrtf(g[36 + d]), EPSN);
        float a[6]; float m = -1e30f;
        #pragma unroll
        for (int e = 0; e < 6; ++e) {
            float kn = fmaxf(sqrtf(g[42 + e]), EPSN);
            a[e] = g[d*6+e] * SCALE / (qn * kn);
            m = fmaxf(m, a[e]);
        }
        float s = 0.f;
        #pragma unroll
        for (int e = 0; e < 6; ++e) { a[e] = expf(a[e]-m); s += a[e]; }
        float inv = 1.f / s;
        #pragma unroll
        for (int e = 0; e < 6; ++e) attn_s[h][d*6+e] = a[e]*inv;
    }
    __syncthreads();

    for (int idx = tid; idx < C*C; idx += blockDim.x) {
        int c = idx / C, c2 = idx % C;
        int h2 = c2 / DH, e = c2 % DH;
        float s = 0.f;
        #pragma unroll
        for (int d = 0; d < 6; ++d)
            s += wproj[c*C + h2*DH + d] * attn_s[h2][d*6+e];
        g_M[b*C*C + idx] = s;
    }
}

/* ===== k_vproj: dw(v) into smem (2 halo chunks) + register-tiled matvec ====
   block = 512 thr, tile = 2 rows x 256 cols = 512 px.
   Phase1: chunkwise 24-ch halo stage + dw -> dvs[48][512].
   Phase2: thread (quad q, group gy): 12 couts x 4 px, k_pw FMA pattern. */
#define VR 2
#define VSR 4
#define VCOL 258
#define VP_NT 512
#define VP_CH 24
#define VP_HALO 0
#define VP_DVS (VP_CH*VSR*VCOL)          /* 24768 */
#define VP_MS (VP_DVS + C*512)           /* +24576 */
#define VP_WDS (VP_MS + C*C)             /* +2304 */
#define VP_SMF (VP_WDS + C*9)            /* 52080 fl = 208320 B */

__global__ __launch_bounds__(VP_NT, 1)
void k_vproj(const float* __restrict__ wdw, float* __restrict__ out)
{
    extern __shared__ float sm[];
    float* halo = sm + VP_HALO;
    float* dvs  = sm + VP_DVS;
    float* MsT  = sm + VP_MS;
    float* wds  = sm + VP_WDS;

    const int tid = threadIdx.x;
    const int strip = blockIdx.x;   /* 0..127 */
    const int b = blockIdx.y;
    const int r0 = strip * VR;

    if (tid < C*9)
        wds[tid] = wdw[(2*C + tid/9)*9 + tid%9];
    for (int i = tid; i < C*C; i += VP_NT) {
        int c = i / C, c2 = i % C;
        MsT[c2*C + c] = g_M[b*C*C + i];     /* transposed: [cin][cout] */
    }

    const int rh = tid >> 8;
    const int col = tid & 255;
    const float* qb = g_qkv + (size_t)b*C3*NPIX + (size_t)(2*C)*NPIX;

    #pragma unroll
    for (int chunk = 0; chunk < 2; ++chunk) {
        const int ch0 = chunk * VP_CH;
        __syncthreads();   /* wds/MsT staged (1st); prev chunk's halo reads done (2nd) */
        #pragma unroll
        for (int it = 0; it < (VP_CH*VSR*256)/VP_NT; ++it) {   /* 48 iters */
            int i = it*VP_NT + tid;
            int chrow = i >> 8;            /* ch*4 + row, 0..95 */
            int cc = i & 255;
            int ch = chrow >> 2;
            int row = chrow & 3;
            int grow = r0 - 1 + row;
            float v = 0.f;
            if ((unsigned)grow < (unsigned)HH)
                v = qb[(size_t)(ch0 + ch)*NPIX + grow*WW + cc];
            halo[chrow*VCOL + cc + 1] = v;
        }
        if (tid < VP_CH*VSR) {
            halo[tid*VCOL] = 0.f;
            halo[tid*VCOL + VCOL - 1] = 0.f;
        }
        __syncthreads();
        #pragma unroll
        for (int ch = 0; ch < VP_CH; ++ch) {
            const float* w = wds + (ch0 + ch)*9;
            const float* p = halo + (ch*VSR + rh)*VCOL + col;
            dvs[(ch0 + ch)*512 + tid] =
                  w[0]*p[0]       + w[1]*p[1]        + w[2]*p[2]
                + w[3]*p[VCOL]    + w[4]*p[VCOL+1]   + w[5]*p[VCOL+2]
                + w[6]*p[2*VCOL]  + w[7]*p[2*VCOL+1] + w[8]*p[2*VCOL+2];
        }
    }
    __syncthreads();

    /* matvec: q = pixel quad (0..127), gy = cout group (0..3) */
    const int q = tid & 127;
    const int gy = tid >> 7;

    float4 acc[12];
    #pragma unroll
    for (int j = 0; j < 12; ++j) acc[j] = make_float4(0.f,0.f,0.f,0.f);

    const float4* dcol = reinterpret_cast<const float4*>(dvs) + q;
    const float*  wrow = MsT + gy*12;

    #pragma unroll 4
    for (int cin = 0; cin < C; ++cin) {
        float4 xv = dcol[cin*128];
        const float4* w4 = reinterpret_cast<const float4*>(wrow + cin*C);
        float4 w0 = w4[0], w1 = w4[1], w2 = w4[2];
        acc[0].x += w0.x*xv.x; acc[0].y += w0.x*xv.y; acc[0].z += w0.x*xv.z; acc[0].w += w0.x*xv.w;
        acc[1].x += w0.y*xv.x; acc[1].y += w0.y*xv.y; acc[1].z += w0.y*xv.z; acc[1].w += w0.y*xv.w;
        acc[2].x += w0.z*xv.x; acc[2].y += w0.z*xv.y; acc[2].z += w0.z*xv.z; acc[2].w += w0.z*xv.w;
        acc[3].x += w0.w*xv.x; acc[3].y += w0.w*xv.y; acc[3].z += w0.w*xv.z; acc[3].w += w0.w*xv.w;
        acc[4].x += w1.x*xv.x; acc[4].y += w1.x*xv.y; acc[4].z += w1.x*xv.z; acc[4].w += w1.x*xv.w;
        acc[5].x += w1.y*xv.x; acc[5].y += w1.y*xv.y; acc[5].z += w1.y*xv.z; acc[5].w += w1.y*xv.w;
        acc[6].x += w1.z*xv.x; acc[6].y += w1.z*xv.y; acc[6].z += w1.z*xv.z; acc[6].w += w1.z*xv.w;
        acc[7].x += w1.w*xv.x; acc[7].y += w1.w*xv.y; acc[7].z += w1.w*xv.z; acc[7].w += w1.w*xv.w;
        acc[8].x += w2.x*xv.x; acc[8].y += w2.x*xv.y; acc[8].z += w2.x*xv.z; acc[8].w += w2.x*xv.w;
        acc[9].x += w2.y*xv.x; acc[9].y += w2.y*xv.y; acc[9].z += w2.y*xv.z; acc[9].w += w2.y*xv.w;
        acc[10].x += w2.z*xv.x; acc[10].y += w2.z*xv.y; acc[10].z += w2.z*xv.z; acc[10].w += w2.z*xv.w;
        acc[11].x += w2.w*xv.x; acc[11].y += w2.w*xv.y; acc[11].z += w2.w*xv.z; acc[11].w += w2.w*xv.w;
    }

    /* quad q covers px q*4..q*4+3 of the 2x256 tile; row = q>>6, col4 = (q&63)*4 */
    float* ob = out + (size_t)b*C*NPIX + (size_t)(r0 + (q >> 6))*WW + (q & 63)*4;
    #pragma unroll
    for (int j = 0; j < 12; ++j) {
        int cout = gy*12 + j;
        *reinterpret_cast<float4*>(ob + (size_t)cout*NPIX) = acc[j];
    }
}

extern "C" void kernel_launch(void* const* d_in, const int* in_sizes, int n_in,
                              void* d_out, int out_size)
{
    const float* x     = (const float*)d_in[0];
    const float* wqkv  = (const float*)d_in[1];
    const float* wdw   = (const float*)d_in[2];
    const float* wproj = (const float*)d_in[3];
    float* out = (float*)d_out;

    cudaFuncSetAttribute(k_pw, cudaFuncAttributeMaxDynamicSharedMemorySize,
                         PW_SMF * (int)sizeof(float));
    cudaFuncSetAttribute(k_dwg, cudaFuncAttributeMaxDynamicSharedMemorySize,
                         DW_SMF * (int)sizeof(float));
    cudaFuncSetAttribute(k_vproj, cudaFuncAttributeMaxDynamicSharedMemorySize,
                         VP_SMF * (int)sizeof(float));

    dim3 gpw(NPIX/PWN, B);
    k_pw<<<gpw, PW_NT, PW_SMF * sizeof(float)>>>(x, wqkv);

    dim3 gdw(NTIL, HEADS, B);
    k_dwg<<<gdw, DW_NT, DW_SMF * sizeof(float)>>>(wdw);

    k_attn<<<B, 384>>>(wproj);

    dim3 gvp(HH/VR, B);
    k_vproj<<<gvp, VP_NT, VP_SMF * sizeof(float)>>>(wdw, out);
}